// round 8
// baseline (speedup 1.0000x reference)
#include <cuda_runtime.h>
#include <cuda_fp16.h>
#include <cstdint>

#define BATCH 32
#define LQN   2048
#define LKN   50
#define DIN   1024
#define DVN   512

typedef __half h16;

// ---------------------------------------------------------------------------
// Scratch (device globals; allocations are forbidden)
// ---------------------------------------------------------------------------
__device__ float g_k[BATCH * LKN * DIN];                         // keys @ W_k (fp32)
__device__ h16  g_UtHi[(size_t)BATCH * DVN * DIN];               // (k^T W_o /32)^T  [B,512,1024]
__device__ h16  g_UtLo[(size_t)BATCH * DVN * DIN];
__device__ h16  g_WqHi[DIN * DIN];                               // Wq (B-side: hi only)
__device__ h16  g_GtHi[(size_t)BATCH * DVN * DIN];               // G^T [B,512,1024]
__device__ h16  g_GtLo[(size_t)BATCH * DVN * DIN];
__device__ h16  g_qHi[(size_t)BATCH * LQN * DIN];                // queries (B-side: hi only)
__device__ h16  g_vTHi[(size_t)BATCH * DIN * LQN];               // values^T (B-side: hi only)
__device__ h16  g_aHi[(size_t)BATCH * DVN * LQN];                // attn split [B,512,2048]
__device__ h16  g_aLo[(size_t)BATCH * DVN * LQN];
__device__ h16  g_THi[(size_t)BATCH * DVN * DIN];                // (attn@values) split [B,512,1024]
__device__ h16  g_TLo[(size_t)BATCH * DVN * DIN];
__device__ h16  g_WvTHi[DIN * DIN];                              // Wv^T (B-side: hi only)

// ---------------------------------------------------------------------------
// Helpers
// ---------------------------------------------------------------------------
__device__ __forceinline__ uint32_t smem_u32(const void* p) {
    uint32_t a;
    asm("{ .reg .u64 t; cvta.to.shared.u64 t, %1; cvt.u32.u64 %0, t; }" : "=r"(a) : "l"(p));
    return a;
}
#define SW128(o) ((o) ^ (((o) >> 3) & 0x70))

__device__ __forceinline__ void cp16(uint32_t dst, const void* src) {
    asm volatile("cp.async.cg.shared.global [%0], [%1], 16;" :: "r"(dst), "l"(src) : "memory");
}
#define CP_COMMIT() asm volatile("cp.async.commit_group;" ::: "memory")
#define CP_WAIT0()  asm volatile("cp.async.wait_group 0;" ::: "memory")
#define CP_WAIT1()  asm volatile("cp.async.wait_group 1;" ::: "memory")

__device__ __forceinline__ void ldsm4(uint32_t& r0, uint32_t& r1, uint32_t& r2, uint32_t& r3, uint32_t a) {
    asm volatile("ldmatrix.sync.aligned.m8n8.x4.shared.b16 {%0,%1,%2,%3}, [%4];"
                 : "=r"(r0), "=r"(r1), "=r"(r2), "=r"(r3) : "r"(a));
}
__device__ __forceinline__ void mma16816(float* d, const uint32_t* a, uint32_t b0, uint32_t b1) {
    asm volatile("mma.sync.aligned.m16n8k16.row.col.f32.f16.f16.f32 "
                 "{%0,%1,%2,%3},{%4,%5,%6,%7},{%8,%9},{%0,%1,%2,%3};"
                 : "+f"(d[0]), "+f"(d[1]), "+f"(d[2]), "+f"(d[3])
                 : "r"(a[0]), "r"(a[1]), "r"(a[2]), "r"(a[3]), "r"(b0), "r"(b1));
}
__device__ __forceinline__ void split2h(float x, h16& h, h16& l) {
    h = __float2half(x);
    l = __float2half(x - __half2float(h));
}
__device__ __forceinline__ uint32_t pack2(h16 a, h16 b) {
    return ((uint32_t)__half_as_ushort(b) << 16) | __half_as_ushort(a);
}

// ---------------------------------------------------------------------------
// HMMA fp16 2-product GEMM:  C[b] = A[b] (MxK) @ B[b]^T  (B is [N,K] K-major)
// A as hi/lo fp16 pair, B as hi fp16 only: C = (ah+al) @ bh^T  (error ~2^-12)
// Block tile 128x128, 8 warps (4M x 2N, warp tile 32x64), K-chunk 64,
// 3-stage cp.async pipeline, SW128 swizzle.
// OUT_MODE 0: fp32 C.  OUT_MODE 1: fp16 hi/lo split C.
// M,N multiples of 128; K multiple of 64 with K/64 >= 2.
// ---------------------------------------------------------------------------
#define ASZ 16384                                // 128 x 64 fp16
#define STAGE_BYTES (3 * ASZ)                    // Ahi | Alo | Bhi
#define MM_SMEM_TOTAL (3 * STAGE_BYTES)          // 147456

template <int OUT_MODE>
__global__ __launch_bounds__(256, 1)
void mma_gemm(const h16* __restrict__ Ahi, const h16* __restrict__ Alo,
              const h16* __restrict__ Bhi,
              float* __restrict__ Cf, h16* __restrict__ Chi, h16* __restrict__ Clo,
              int M, int N, int K,
              long long sA, long long sB, long long sC, int ldc)
{
    extern __shared__ char smem[];
    const uint32_t sb = smem_u32(smem);
    const int tid = threadIdx.x;
    const int lane = tid & 31;
    const int wid = tid >> 5;
    const int warpM = wid & 3;            // 4 warps in M (32 rows each)
    const int warpN = wid >> 2;           // 2 warps in N (64 cols each)
    const int bz = blockIdx.z;
    const int bm = blockIdx.y * 128;
    const int bn = blockIdx.x * 128;

    const char* gA0 = (const char*)(Ahi + (long long)bz * sA + (long long)bm * K);
    const char* gA1 = (const char*)(Alo + (long long)bz * sA + (long long)bm * K);
    const char* gB0 = (const char*)(Bhi + (long long)bz * sB + (long long)bn * K);

    const int cr = tid >> 3;              // 0..31 base row
    const int cs = (tid & 7) << 4;        // byte col within 128B row
    const long long Kb = (long long)K * 2;
    const int NC = K >> 6;

    float acc[2][8][4];
    #pragma unroll
    for (int mt = 0; mt < 2; mt++)
        #pragma unroll
        for (int nt = 0; nt < 8; nt++)
            #pragma unroll
            for (int j = 0; j < 4; j++) acc[mt][nt][j] = 0.0f;

    // Prologue: issue chunks 0 and 1
    #pragma unroll
    for (int pc = 0; pc < 2; pc++) {
        uint32_t st = sb + pc * STAGE_BYTES;
        const int k0b = pc << 7;
        #pragma unroll
        for (int i = 0; i < 4; i++) {
            int r = cr + i * 32;
            uint32_t so = SW128(r * 128 + cs);
            long long go = (long long)r * Kb + cs + k0b;
            cp16(st + so,           gA0 + go);
            cp16(st + ASZ + so,     gA1 + go);
            cp16(st + 2 * ASZ + so, gB0 + go);
        }
        CP_COMMIT();
    }

    // ldmatrix lane coordinates
    const int mrowA = (lane & 7) + ((lane >> 3) & 1) * 8;
    const int kcA   = (lane >> 4) * 16;
    const int nrowB = (lane & 7) + ((lane >> 4) << 3);
    const int kcB   = ((lane >> 3) & 1) * 16;

    int stage = 0;
    for (int c = 0; c < NC; c++) {
        if (c + 1 < NC) { CP_WAIT1(); } else { CP_WAIT0(); }
        __syncthreads();

        if (c + 2 < NC) {
            int ps = stage + 2; if (ps >= 3) ps -= 3;
            uint32_t st = sb + ps * STAGE_BYTES;
            const int k0b = (c + 2) << 7;
            #pragma unroll
            for (int i = 0; i < 4; i++) {
                int r = cr + i * 32;
                uint32_t so = SW128(r * 128 + cs);
                long long go = (long long)r * Kb + cs + k0b;
                cp16(st + so,           gA0 + go);
                cp16(st + ASZ + so,     gA1 + go);
                cp16(st + 2 * ASZ + so, gB0 + go);
            }
            CP_COMMIT();
        }

        const uint32_t stg = sb + stage * STAGE_BYTES;
        const uint32_t bA0 = stg;
        const uint32_t bA1 = stg + ASZ;
        const uint32_t bB0 = stg + 2 * ASZ;

        #pragma unroll
        for (int ks = 0; ks < 4; ks++) {
            uint32_t ah[2][4], al[2][4];
            #pragma unroll
            for (int mt = 0; mt < 2; mt++) {
                uint32_t off = SW128((warpM * 32 + mt * 16 + mrowA) * 128 + ks * 32 + kcA);
                ldsm4(ah[mt][0], ah[mt][1], ah[mt][2], ah[mt][3], bA0 + off);
                ldsm4(al[mt][0], al[mt][1], al[mt][2], al[mt][3], bA1 + off);
            }
            uint32_t bh[8][2];
            #pragma unroll
            for (int np = 0; np < 4; np++) {
                uint32_t off = SW128((warpN * 64 + np * 16 + nrowB) * 128 + ks * 32 + kcB);
                ldsm4(bh[2*np][0], bh[2*np][1], bh[2*np+1][0], bh[2*np+1][1], bB0 + off);
            }
            #pragma unroll
            for (int mt = 0; mt < 2; mt++)
                #pragma unroll
                for (int nt = 0; nt < 8; nt++) {
                    mma16816(acc[mt][nt], ah[mt], bh[nt][0], bh[nt][1]);
                    mma16816(acc[mt][nt], al[mt], bh[nt][0], bh[nt][1]);
                }
        }
        __syncthreads();
        if (++stage == 3) stage = 0;
    }

    // Epilogue: direct global stores
    const long long cbase = (long long)bz * sC;
    #pragma unroll
    for (int mt = 0; mt < 2; mt++) {
        const int r0 = bm + warpM * 32 + mt * 16 + (lane >> 2);
        #pragma unroll
        for (int half = 0; half < 2; half++) {
            const int r = r0 + half * 8;
            const long long rowoff = cbase + (long long)r * ldc + bn + warpN * 64 + (lane & 3) * 2;
            #pragma unroll
            for (int nt = 0; nt < 8; nt++) {
                float x0 = acc[mt][nt][half * 2 + 0];
                float x1 = acc[mt][nt][half * 2 + 1];
                long long off = rowoff + nt * 8;
                if (OUT_MODE == 0) {
                    *(float2*)(Cf + off) = make_float2(x0, x1);
                } else {
                    h16 sh0, sl0, sh1, sl1;
                    split2h(x0, sh0, sl0);
                    split2h(x1, sh1, sl1);
                    *(uint32_t*)(Chi + off) = pack2(sh0, sh1);
                    *(uint32_t*)(Clo + off) = pack2(sl0, sl1);
                }
            }
        }
    }
}

// ---------------------------------------------------------------------------
// fp32 SIMT GEMM for the small K-projection (M=50): C = A(MxK) @ B(KxN)
// ---------------------------------------------------------------------------
__global__ __launch_bounds__(256)
void gemm128(const float* __restrict__ A, const float* __restrict__ Bm,
             float* __restrict__ C, int M, int N, int K,
             long long sA, long long sB, long long sC, int lda, int ldb, int ldc)
{
    const int b = blockIdx.z;
    A += (long long)b * sA; Bm += (long long)b * sB; C += (long long)b * sC;
    const int bm = blockIdx.y * 128, bn = blockIdx.x * 128;
    __shared__ float As[16][128], Bs[16][128];
    const int tid = threadIdx.x, tx = tid & 15, ty = tid >> 4;
    float acc[8][8];
    #pragma unroll
    for (int i = 0; i < 8; i++)
        #pragma unroll
        for (int j = 0; j < 8; j++) acc[i][j] = 0.0f;

    for (int k0 = 0; k0 < K; k0 += 16) {
        #pragma unroll
        for (int l = 0; l < 2; l++) {
            int t = tid + l * 256, row = t >> 2, col = (t & 3) << 2;
            float4 v = make_float4(0.f, 0.f, 0.f, 0.f);
            if (bm + row < M) v = *(const float4*)(A + (long long)(bm + row) * lda + k0 + col);
            As[col + 0][row] = v.x; As[col + 1][row] = v.y;
            As[col + 2][row] = v.z; As[col + 3][row] = v.w;
        }
        #pragma unroll
        for (int l = 0; l < 2; l++) {
            int t = tid + l * 256, row = t >> 5, col = (t & 31) << 2;
            *(float4*)&Bs[row][col] = *(const float4*)(Bm + (long long)(k0 + row) * ldb + bn + col);
        }
        __syncthreads();
        #pragma unroll
        for (int kk = 0; kk < 16; kk++) {
            float a[8], bb[8];
            float4 a0 = *(const float4*)&As[kk][ty * 8];
            float4 a1 = *(const float4*)&As[kk][ty * 8 + 4];
            a[0]=a0.x; a[1]=a0.y; a[2]=a0.z; a[3]=a0.w; a[4]=a1.x; a[5]=a1.y; a[6]=a1.z; a[7]=a1.w;
            float4 b0 = *(const float4*)&Bs[kk][tx * 8];
            float4 b1 = *(const float4*)&Bs[kk][tx * 8 + 4];
            bb[0]=b0.x; bb[1]=b0.y; bb[2]=b0.z; bb[3]=b0.w; bb[4]=b1.x; bb[5]=b1.y; bb[6]=b1.z; bb[7]=b1.w;
            #pragma unroll
            for (int i = 0; i < 8; i++)
                #pragma unroll
                for (int j = 0; j < 8; j++) acc[i][j] = fmaf(a[i], bb[j], acc[i][j]);
        }
        __syncthreads();
    }
    #pragma unroll
    for (int i = 0; i < 8; i++) {
        int m = bm + ty * 8 + i;
        if (m >= M) continue;
        #pragma unroll
        for (int j = 0; j < 8; j++) C[(long long)m * ldc + bn + tx * 8 + j] = acc[i][j];
    }
}

// ---------------------------------------------------------------------------
// Ut[b,v,h] = (1/32) * sum_k (keys@Wk)[b,k,h] * Wo[k,v] -> fp16 hi/lo, packed
// ---------------------------------------------------------------------------
__global__ __launch_bounds__(256)
void u_kernel(const float* __restrict__ kmat, const float* __restrict__ Wo,
              h16* __restrict__ uhi, h16* __restrict__ ulo)
{
    const int b = blockIdx.z, hb = blockIdx.y * 32, v0 = blockIdx.x * 32;
    __shared__ float ks[LKN][32], wo[LKN][32];
    const int tid = threadIdx.x;
    for (int i = tid; i < LKN * 32; i += 256) {
        int kk = i >> 5, c = i & 31;
        ks[kk][c] = kmat[((long long)b * LKN + kk) * DIN + hb + c];
        wo[kk][c] = Wo[kk * DVN + v0 + c];
    }
    __syncthreads();
    const int hp = (tid & 15) * 2;      // h pair within 32-col block
    const int vi = tid >> 4;            // 0..15, covers v {vi, vi+16}
    float a00 = 0.f, a01 = 0.f, a10 = 0.f, a11 = 0.f;
    for (int kk = 0; kk < LKN; kk++) {
        float k0 = ks[kk][hp], k1 = ks[kk][hp + 1];
        float w0 = wo[kk][vi], w1 = wo[kk][vi + 16];
        a00 = fmaf(k0, w0, a00); a01 = fmaf(k1, w0, a01);
        a10 = fmaf(k0, w1, a10); a11 = fmaf(k1, w1, a11);
    }
    const float s = 0.03125f;
    #pragma unroll
    for (int sv = 0; sv < 2; sv++) {
        float x0 = (sv ? a10 : a00) * s;
        float x1 = (sv ? a11 : a01) * s;
        h16 sh0, sl0, sh1, sl1;
        split2h(x0, sh0, sl0);
        split2h(x1, sh1, sl1);
        long long off = ((long long)b * DVN + v0 + vi + sv * 16) * DIN + hb + hp;
        *(uint32_t*)(uhi + off) = pack2(sh0, sh1);
        *(uint32_t*)(ulo + off) = pack2(sl0, sl1);
    }
}

// ---------------------------------------------------------------------------
// Elementwise fp32 -> fp16 hi (n multiple of 2048)
// ---------------------------------------------------------------------------
__global__ __launch_bounds__(256)
void split_plain_hi(const float* __restrict__ in, h16* __restrict__ hi)
{
    long long i = ((long long)blockIdx.x * 256 + threadIdx.x) * 8;
    float4 a = *(const float4*)(in + i);
    float4 b = *(const float4*)(in + i + 4);
    union { h16 h[8]; uint4 u; } H;
    H.h[0] = __float2half(a.x); H.h[1] = __float2half(a.y);
    H.h[2] = __float2half(a.z); H.h[3] = __float2half(a.w);
    H.h[4] = __float2half(b.x); H.h[5] = __float2half(b.y);
    H.h[6] = __float2half(b.z); H.h[7] = __float2half(b.w);
    *(uint4*)(hi + i) = H.u;
}

// ---------------------------------------------------------------------------
// Tiled transpose (hi only): in [R,C] fp32 -> out [C,R] fp16 (per batch)
// Tile 64(R) x 32(C). Packed uint32 stores (2 fp16 along R).
// ---------------------------------------------------------------------------
__global__ __launch_bounds__(256)
void split_trans_hi(const float* __restrict__ in, h16* __restrict__ hi, int R, int C)
{
    const int b = blockIdx.z;
    const long long n = (long long)R * C;
    in += b * n; hi += b * n;
    const int r0 = blockIdx.y * 64, c0 = blockIdx.x * 32;
    __shared__ float t[32][65];
    const int lane = threadIdx.x & 31, w = threadIdx.x >> 5;
    #pragma unroll
    for (int i = 0; i < 8; i++) {
        int row = w * 8 + i;
        t[lane][row] = in[(long long)(r0 + row) * C + c0 + lane];
    }
    __syncthreads();
    #pragma unroll
    for (int p = 0; p < 4; p++) {
        int idx = threadIdx.x + p * 256;
        int c = idx >> 5;
        int rp = (idx & 31) * 2;
        h16 x0 = __float2half(t[c][rp]);
        h16 x1 = __float2half(t[c][rp + 1]);
        *(uint32_t*)(hi + (long long)(c0 + c) * R + r0 + rp) = pack2(x0, x1);
    }
}

// ---------------------------------------------------------------------------
// Masked softmax over q (2048) per (b,v) row; emits fp16 hi/lo of attn too.
// Thread handles 8 contiguous q.
// ---------------------------------------------------------------------------
__global__ __launch_bounds__(256)
void softmax_mask(float* __restrict__ attn, const int* __restrict__ valid,
                  h16* __restrict__ ahi, h16* __restrict__ alo)
{
    const long long row = blockIdx.x;
    const int b = (int)(row / DVN);
    const int vl = valid[b];
    float* p = attn + row * (long long)LQN;
    const int tid = threadIdx.x;
    const int q0 = tid * 8;

    float v[8];
    {
        float4 a = *(const float4*)(p + q0);
        float4 c = *(const float4*)(p + q0 + 4);
        v[0]=a.x; v[1]=a.y; v[2]=a.z; v[3]=a.w;
        v[4]=c.x; v[5]=c.y; v[6]=c.z; v[7]=c.w;
    }
    float mx = -3.4e38f;
    #pragma unroll
    for (int i = 0; i < 8; i++) {
        v[i] = (q0 + i < vl) ? v[i] : -1000000.0f;
        mx = fmaxf(mx, v[i]);
    }
    __shared__ float red[256];
    red[tid] = mx; __syncthreads();
    for (int s = 128; s > 0; s >>= 1) { if (tid < s) red[tid] = fmaxf(red[tid], red[tid + s]); __syncthreads(); }
    mx = red[0]; __syncthreads();
    float sum = 0.0f;
    #pragma unroll
    for (int i = 0; i < 8; i++) { v[i] = expf(v[i] - mx); sum += v[i]; }
    red[tid] = sum; __syncthreads();
    for (int s = 128; s > 0; s >>= 1) { if (tid < s) red[tid] += red[tid + s]; __syncthreads(); }
    const float inv = 1.0f / red[0];

    union { h16 h[8]; uint4 u; } H, L;
    #pragma unroll
    for (int i = 0; i < 8; i++) {
        v[i] *= inv;
        split2h(v[i], H.h[i], L.h[i]);
    }
    *(float4*)(p + q0)     = make_float4(v[0], v[1], v[2], v[3]);
    *(float4*)(p + q0 + 4) = make_float4(v[4], v[5], v[6], v[7]);
    *(uint4*)(ahi + row * LQN + q0) = H.u;
    *(uint4*)(alo + row * LQN + q0) = L.u;
}

// ---------------------------------------------------------------------------
extern "C" void kernel_launch(void* const* d_in, const int* in_sizes, int n_in,
                              void* d_out, int out_size)
{
    const float* queries = (const float*)d_in[0];
    const float* keys    = (const float*)d_in[1];
    const float* values  = (const float*)d_in[2];
    const int*   valid   = (const int*)  d_in[3];
    const float* Wq      = (const float*)d_in[4];
    const float* Wk      = (const float*)d_in[5];
    const float* Wv      = (const float*)d_in[6];
    const float* Wo      = (const float*)d_in[7];

    float* out  = (float*)d_out;                         // [32,512,1024]
    float* attn = out + (size_t)BATCH * DVN * DIN;       // [32,512,2048]

    float *pk;
    h16 *pUtH, *pUtL, *pWqH, *pGtH, *pGtL, *pqH;
    h16 *pvTH, *paH, *paL, *pTH, *pTL, *pWvTH;
    cudaGetSymbolAddress((void**)&pk,   g_k);
    cudaGetSymbolAddress((void**)&pUtH, g_UtHi); cudaGetSymbolAddress((void**)&pUtL, g_UtLo);
    cudaGetSymbolAddress((void**)&pWqH, g_WqHi);
    cudaGetSymbolAddress((void**)&pGtH, g_GtHi); cudaGetSymbolAddress((void**)&pGtL, g_GtLo);
    cudaGetSymbolAddress((void**)&pqH,  g_qHi);
    cudaGetSymbolAddress((void**)&pvTH, g_vTHi);
    cudaGetSymbolAddress((void**)&paH,  g_aHi);  cudaGetSymbolAddress((void**)&paL,  g_aLo);
    cudaGetSymbolAddress((void**)&pTH,  g_THi);  cudaGetSymbolAddress((void**)&pTL,  g_TLo);
    cudaGetSymbolAddress((void**)&pWvTH, g_WvTHi);

    cudaFuncSetAttribute(mma_gemm<0>, cudaFuncAttributeMaxDynamicSharedMemorySize, MM_SMEM_TOTAL);
    cudaFuncSetAttribute(mma_gemm<1>, cudaFuncAttributeMaxDynamicSharedMemorySize, MM_SMEM_TOTAL);

    // K1: k = keys @ W_k (fp32 SIMT, small M=50)
    gemm128<<<dim3(DIN / 128, 1, BATCH), 256>>>(
        keys, Wk, pk, LKN, DIN, DIN,
        (long long)LKN * DIN, 0, (long long)LKN * DIN, DIN, DIN, DIN);

    // K2: Ut = (k^T @ W_o / 32)^T  -> fp16 hi/lo [B,512,1024]
    u_kernel<<<dim3(DVN / 32, DIN / 32, BATCH), 256>>>(pk, Wo, pUtH, pUtL);

    // Wq -> hi only
    split_plain_hi<<<(DIN * DIN) / 2048, 256>>>(Wq, pWqH);

    // K3: Gt[v,i] = Ut[v,:] . Wq[i,:]   (M=512, N=1024, K=1024) -> fp16 split
    mma_gemm<1><<<dim3(DIN / 128, DVN / 128, BATCH), 256, MM_SMEM_TOTAL>>>(
        pUtH, pUtL, pWqH, nullptr, pGtH, pGtL,
        DVN, DIN, DIN, (long long)DVN * DIN, 0, (long long)DVN * DIN, DIN);

    // queries -> hi only
    split_plain_hi<<<(int)(((long long)BATCH * LQN * DIN) / 2048), 256>>>(queries, pqH);

    // K4: scores[v,q] = Gt[v,:] . queries[q,:]  (M=512, N=2048, K=1024) -> fp32 attn buf
    mma_gemm<0><<<dim3(LQN / 128, DVN / 128, BATCH), 256, MM_SMEM_TOTAL>>>(
        pGtH, pGtL, pqH, attn, nullptr, nullptr,
        DVN, LQN, DIN, (long long)DVN * DIN, (long long)LQN * DIN, (long long)DVN * LQN, LQN);

    // K5: masked softmax over q (emits fp16 split of attn)
    softmax_mask<<<BATCH * DVN, 256>>>(attn, valid, paH, paL);

    // values -> transpose, hi only: vT [B,1024,2048]
    split_trans_hi<<<dim3(DIN / 32, LQN / 64, BATCH), 256>>>(values, pvTH, LQN, DIN);

    // K6: T[v,d] = attn[v,:] . vT[d,:]  (M=512, N=1024, K=2048) -> fp16 split
    mma_gemm<1><<<dim3(DIN / 128, DVN / 128, BATCH), 256, MM_SMEM_TOTAL>>>(
        paH, paL, pvTH, nullptr, pTH, pTL,
        DVN, DIN, LQN, (long long)DVN * LQN, (long long)DIN * LQN, (long long)DVN * DIN, DIN);

    // Wv -> transpose, hi only: WvT [1024,1024]
    split_trans_hi<<<dim3(DIN / 32, DIN / 64, 1), 256>>>(Wv, pWvTH, DIN, DIN);

    // K7: out[v,h] = T[v,:] . WvT[h,:]  (M=512, N=1024, K=1024) -> fp32 out
    mma_gemm<0><<<dim3(DIN / 128, DVN / 128, BATCH), 256, MM_SMEM_TOTAL>>>(
        pTH, pTL, pWvTH, out, nullptr, nullptr,
        DVN, DIN, DIN, (long long)DVN * DIN, 0, (long long)DVN * DIN, DIN);
}

// round 9
// speedup vs baseline: 1.2097x; 1.2097x over previous
#include <cuda_runtime.h>
#include <cuda_bf16.h>
#include <cstdint>

#define BATCH 32
#define LQN   2048
#define LKN   50
#define DIN   1024
#define DVN   512

typedef __nv_bfloat16 bf16;

// ---------------------------------------------------------------------------
// Scratch (device globals; allocations are forbidden)
// ---------------------------------------------------------------------------
__device__ float g_k[BATCH * LKN * DIN];                         // keys @ W_k (fp32)
__device__ bf16  g_UtHi[(size_t)BATCH * DVN * DIN];              // (k^T W_o /32)^T  [B,512,1024]
__device__ bf16  g_UtLo[(size_t)BATCH * DVN * DIN];
__device__ bf16  g_WqHi[DIN * DIN];
__device__ bf16  g_WqLo[DIN * DIN];
__device__ bf16  g_GtHi[(size_t)BATCH * DVN * DIN];              // G^T [B,512,1024]
__device__ bf16  g_GtLo[(size_t)BATCH * DVN * DIN];
__device__ bf16  g_qHi[(size_t)BATCH * LQN * DIN];               // queries split [B,2048,1024]
__device__ bf16  g_qLo[(size_t)BATCH * LQN * DIN];
__device__ bf16  g_vTHi[(size_t)BATCH * DIN * LQN];              // values^T split [B,1024,2048]
__device__ bf16  g_vTLo[(size_t)BATCH * DIN * LQN];
__device__ bf16  g_aHi[(size_t)BATCH * DVN * LQN];               // attn split [B,512,2048]
__device__ bf16  g_aLo[(size_t)BATCH * DVN * LQN];
__device__ bf16  g_THi[(size_t)BATCH * DVN * DIN];               // (attn@values) split [B,512,1024]
__device__ bf16  g_TLo[(size_t)BATCH * DVN * DIN];
__device__ bf16  g_WvTHi[DIN * DIN];                             // Wv^T split
__device__ bf16  g_WvTLo[DIN * DIN];

// ---------------------------------------------------------------------------
// Helpers
// ---------------------------------------------------------------------------
__device__ __forceinline__ uint32_t smem_u32(const void* p) {
    uint32_t a;
    asm("{ .reg .u64 t; cvta.to.shared.u64 t, %1; cvt.u32.u64 %0, t; }" : "=r"(a) : "l"(p));
    return a;
}
#define SW128(o) ((o) ^ (((o) >> 3) & 0x70))

__device__ __forceinline__ void cp16(uint32_t dst, const void* src) {
    asm volatile("cp.async.cg.shared.global [%0], [%1], 16;" :: "r"(dst), "l"(src) : "memory");
}
#define CP_COMMIT() asm volatile("cp.async.commit_group;" ::: "memory")
#define CP_WAIT0()  asm volatile("cp.async.wait_group 0;" ::: "memory")

__device__ __forceinline__ void ldsm4(uint32_t& r0, uint32_t& r1, uint32_t& r2, uint32_t& r3, uint32_t a) {
    asm volatile("ldmatrix.sync.aligned.m8n8.x4.shared.b16 {%0,%1,%2,%3}, [%4];"
                 : "=r"(r0), "=r"(r1), "=r"(r2), "=r"(r3) : "r"(a));
}
__device__ __forceinline__ void mma16816(float* d, const uint32_t* a, uint32_t b0, uint32_t b1) {
    asm volatile("mma.sync.aligned.m16n8k16.row.col.f32.bf16.bf16.f32 "
                 "{%0,%1,%2,%3},{%4,%5,%6,%7},{%8,%9},{%0,%1,%2,%3};"
                 : "+f"(d[0]), "+f"(d[1]), "+f"(d[2]), "+f"(d[3])
                 : "r"(a[0]), "r"(a[1]), "r"(a[2]), "r"(a[3]), "r"(b0), "r"(b1));
}
__device__ __forceinline__ void split2(float x, bf16& h, bf16& l) {
    h = __float2bfloat16(x);
    l = __float2bfloat16(x - __bfloat162float(h));
}
__device__ __forceinline__ uint32_t pack2b(bf16 a, bf16 b) {
    return ((uint32_t)__bfloat16_as_ushort(b) << 16) | __bfloat16_as_ushort(a);
}

// ---------------------------------------------------------------------------
// HMMA bf16-split GEMM:  C[b] = A[b] (MxK) @ B[b]^T  (B is [N,K] K-major)
// A,B as hi/lo bf16 pairs; 3-product split (hi*hi + lo*hi + hi*lo), fp32 acc.
// Block tile 128x128, 8 warps (4M x 2N), K-chunk 64, 2-stage cp.async,
// SW128 swizzle.  (Proven R4 core — do not "improve" without evidence.)
// OUT_MODE 0: fp32 C.  OUT_MODE 1: bf16 hi/lo split C.
// ---------------------------------------------------------------------------
#define STAGE_BYTES 65536        // Ahi,Alo,Bhi,Blo -- 4 x 16KB
#define MM_SMEM_TOTAL (2 * STAGE_BYTES)

template <int OUT_MODE>
__global__ __launch_bounds__(256, 1)
void mma_gemm(const bf16* __restrict__ Ahi, const bf16* __restrict__ Alo,
              const bf16* __restrict__ Bhi, const bf16* __restrict__ Blo,
              float* __restrict__ Cf, bf16* __restrict__ Chi, bf16* __restrict__ Clo,
              int M, int N, int K,
              long long sA, long long sB, long long sC, int ldc)
{
    extern __shared__ char smem[];
    const uint32_t sb = smem_u32(smem);
    const int tid = threadIdx.x;
    const int lane = tid & 31;
    const int wid = tid >> 5;
    const int warpM = wid & 3;
    const int warpN = wid >> 2;
    const int bz = blockIdx.z;
    const int bm = blockIdx.y * 128;
    const int bn = blockIdx.x * 128;

    const char* gsrc[4];
    gsrc[0] = (const char*)(Ahi + (long long)bz * sA + (long long)bm * K);
    gsrc[1] = (const char*)(Alo + (long long)bz * sA + (long long)bm * K);
    gsrc[2] = (const char*)(Bhi + (long long)bz * sB + (long long)bn * K);
    gsrc[3] = (const char*)(Blo + (long long)bz * sB + (long long)bn * K);

    const int cr = tid >> 3;
    const int cs = (tid & 7) << 4;

    float acc[2][8][4];
    #pragma unroll
    for (int mt = 0; mt < 2; mt++)
        #pragma unroll
        for (int nt = 0; nt < 8; nt++)
            #pragma unroll
            for (int j = 0; j < 4; j++) acc[mt][nt][j] = 0.0f;

    const long long Kb = (long long)K * 2;
    const int NC = K >> 6;

    {
        #pragma unroll
        for (int t = 0; t < 4; t++) {
            const char* s = gsrc[t];
            uint32_t d = sb + t * 16384;
            #pragma unroll
            for (int i = 0; i < 4; i++) {
                int r = cr + i * 32;
                cp16(d + SW128(r * 128 + cs), s + (long long)r * Kb + cs);
            }
        }
        CP_COMMIT();
    }

    const int mrowA = (lane & 7) + ((lane >> 3) & 1) * 8;
    const int kcA   = (lane >> 4) * 16;
    const int nrowB = (lane & 7) + ((lane >> 4) << 3);
    const int kcB   = ((lane >> 3) & 1) * 16;

    for (int c = 0; c < NC; c++) {
        CP_WAIT0();
        __syncthreads();

        if (c + 1 < NC) {
            const int k0b = (c + 1) << 7;
            uint32_t st = sb + ((c + 1) & 1) * STAGE_BYTES;
            #pragma unroll
            for (int t = 0; t < 4; t++) {
                const char* s = gsrc[t] + k0b;
                uint32_t d = st + t * 16384;
                #pragma unroll
                for (int i = 0; i < 4; i++) {
                    int r = cr + i * 32;
                    cp16(d + SW128(r * 128 + cs), s + (long long)r * Kb + cs);
                }
            }
            CP_COMMIT();
        }

        const uint32_t stg = sb + (c & 1) * STAGE_BYTES;
        const uint32_t bA0 = stg;
        const uint32_t bA1 = stg + 16384;
        const uint32_t bB0 = stg + 32768;
        const uint32_t bB1 = stg + 49152;

        #pragma unroll
        for (int ks = 0; ks < 4; ks++) {
            uint32_t ah[2][4], al[2][4];
            #pragma unroll
            for (int mt = 0; mt < 2; mt++) {
                uint32_t off = SW128((warpM * 32 + mt * 16 + mrowA) * 128 + ks * 32 + kcA);
                ldsm4(ah[mt][0], ah[mt][1], ah[mt][2], ah[mt][3], bA0 + off);
                ldsm4(al[mt][0], al[mt][1], al[mt][2], al[mt][3], bA1 + off);
            }
            uint32_t bh[8][2], bl[8][2];
            #pragma unroll
            for (int np = 0; np < 4; np++) {
                uint32_t off = SW128((warpN * 64 + np * 16 + nrowB) * 128 + ks * 32 + kcB);
                ldsm4(bh[2*np][0], bh[2*np][1], bh[2*np+1][0], bh[2*np+1][1], bB0 + off);
                ldsm4(bl[2*np][0], bl[2*np][1], bl[2*np+1][0], bl[2*np+1][1], bB1 + off);
            }
            #pragma unroll
            for (int mt = 0; mt < 2; mt++)
                #pragma unroll
                for (int nt = 0; nt < 8; nt++) {
                    mma16816(acc[mt][nt], ah[mt], bh[nt][0], bh[nt][1]);
                    mma16816(acc[mt][nt], al[mt], bh[nt][0], bh[nt][1]);
                    mma16816(acc[mt][nt], ah[mt], bl[nt][0], bl[nt][1]);
                }
        }
        __syncthreads();
    }

    const long long cbase = (long long)bz * sC;
    #pragma unroll
    for (int mt = 0; mt < 2; mt++) {
        const int r0 = bm + warpM * 32 + mt * 16 + (lane >> 2);
        #pragma unroll
        for (int half = 0; half < 2; half++) {
            const int r = r0 + half * 8;
            const long long rowoff = cbase + (long long)r * ldc + bn + warpN * 64 + (lane & 3) * 2;
            #pragma unroll
            for (int nt = 0; nt < 8; nt++) {
                float x0 = acc[mt][nt][half * 2 + 0];
                float x1 = acc[mt][nt][half * 2 + 1];
                long long off = rowoff + nt * 8;
                if (OUT_MODE == 0) {
                    *(float2*)(Cf + off) = make_float2(x0, x1);
                } else {
                    bf16 sh0, sl0, sh1, sl1;
                    split2(x0, sh0, sl0);
                    split2(x1, sh1, sl1);
                    *(uint32_t*)(Chi + off) = pack2b(sh0, sh1);
                    *(uint32_t*)(Clo + off) = pack2b(sl0, sl1);
                }
            }
        }
    }
}

// ---------------------------------------------------------------------------
// fp32 SIMT GEMM for the small K-projection (M=50): C = A(MxK) @ B(KxN)
// ---------------------------------------------------------------------------
__global__ __launch_bounds__(256)
void gemm128(const float* __restrict__ A, const float* __restrict__ Bm,
             float* __restrict__ C, int M, int N, int K,
             long long sA, long long sB, long long sC, int lda, int ldb, int ldc)
{
    const int b = blockIdx.z;
    A += (long long)b * sA; Bm += (long long)b * sB; C += (long long)b * sC;
    const int bm = blockIdx.y * 128, bn = blockIdx.x * 128;
    __shared__ float As[16][128], Bs[16][128];
    const int tid = threadIdx.x, tx = tid & 15, ty = tid >> 4;
    float acc[8][8];
    #pragma unroll
    for (int i = 0; i < 8; i++)
        #pragma unroll
        for (int j = 0; j < 8; j++) acc[i][j] = 0.0f;

    for (int k0 = 0; k0 < K; k0 += 16) {
        #pragma unroll
        for (int l = 0; l < 2; l++) {
            int t = tid + l * 256, row = t >> 2, col = (t & 3) << 2;
            float4 v = make_float4(0.f, 0.f, 0.f, 0.f);
            if (bm + row < M) v = *(const float4*)(A + (long long)(bm + row) * lda + k0 + col);
            As[col + 0][row] = v.x; As[col + 1][row] = v.y;
            As[col + 2][row] = v.z; As[col + 3][row] = v.w;
        }
        #pragma unroll
        for (int l = 0; l < 2; l++) {
            int t = tid + l * 256, row = t >> 5, col = (t & 31) << 2;
            *(float4*)&Bs[row][col] = *(const float4*)(Bm + (long long)(k0 + row) * ldb + bn + col);
        }
        __syncthreads();
        #pragma unroll
        for (int kk = 0; kk < 16; kk++) {
            float a[8], bb[8];
            float4 a0 = *(const float4*)&As[kk][ty * 8];
            float4 a1 = *(const float4*)&As[kk][ty * 8 + 4];
            a[0]=a0.x; a[1]=a0.y; a[2]=a0.z; a[3]=a0.w; a[4]=a1.x; a[5]=a1.y; a[6]=a1.z; a[7]=a1.w;
            float4 b0 = *(const float4*)&Bs[kk][tx * 8];
            float4 b1 = *(const float4*)&Bs[kk][tx * 8 + 4];
            bb[0]=b0.x; bb[1]=b0.y; bb[2]=b0.z; bb[3]=b0.w; bb[4]=b1.x; bb[5]=b1.y; bb[6]=b1.z; bb[7]=b1.w;
            #pragma unroll
            for (int i = 0; i < 8; i++)
                #pragma unroll
                for (int j = 0; j < 8; j++) acc[i][j] = fmaf(a[i], bb[j], acc[i][j]);
        }
        __syncthreads();
    }
    #pragma unroll
    for (int i = 0; i < 8; i++) {
        int m = bm + ty * 8 + i;
        if (m >= M) continue;
        #pragma unroll
        for (int j = 0; j < 8; j++) C[(long long)m * ldc + bn + tx * 8 + j] = acc[i][j];
    }
}

// ---------------------------------------------------------------------------
// Ut[b,v,h] = (1/32) * sum_k (keys@Wk)[b,k,h] * Wo[k,v] -> bf16 hi/lo, packed
// ---------------------------------------------------------------------------
__global__ __launch_bounds__(256)
void u_kernel(const float* __restrict__ kmat, const float* __restrict__ Wo,
              bf16* __restrict__ uhi, bf16* __restrict__ ulo)
{
    const int b = blockIdx.z, hb = blockIdx.y * 32, v0 = blockIdx.x * 32;
    __shared__ float ks[LKN][32], wo[LKN][32];
    const int tid = threadIdx.x;
    for (int i = tid; i < LKN * 32; i += 256) {
        int kk = i >> 5, c = i & 31;
        ks[kk][c] = kmat[((long long)b * LKN + kk) * DIN + hb + c];
        wo[kk][c] = Wo[kk * DVN + v0 + c];
    }
    __syncthreads();
    const int hp = (tid & 15) * 2;
    const int vi = tid >> 4;
    float a00 = 0.f, a01 = 0.f, a10 = 0.f, a11 = 0.f;
    for (int kk = 0; kk < LKN; kk++) {
        float k0 = ks[kk][hp], k1 = ks[kk][hp + 1];
        float w0 = wo[kk][vi], w1 = wo[kk][vi + 16];
        a00 = fmaf(k0, w0, a00); a01 = fmaf(k1, w0, a01);
        a10 = fmaf(k0, w1, a10); a11 = fmaf(k1, w1, a11);
    }
    const float s = 0.03125f;
    #pragma unroll
    for (int sv = 0; sv < 2; sv++) {
        float x0 = (sv ? a10 : a00) * s;
        float x1 = (sv ? a11 : a01) * s;
        bf16 sh0, sl0, sh1, sl1;
        split2(x0, sh0, sl0);
        split2(x1, sh1, sl1);
        long long off = ((long long)b * DVN + v0 + vi + sv * 16) * DIN + hb + hp;
        *(uint32_t*)(uhi + off) = pack2b(sh0, sh1);
        *(uint32_t*)(ulo + off) = pack2b(sl0, sl1);
    }
}

// ---------------------------------------------------------------------------
// Elementwise fp32 -> bf16 hi/lo (n multiple of 2048); uint4 stores
// ---------------------------------------------------------------------------
__global__ __launch_bounds__(256)
void split_plain(const float* __restrict__ in, bf16* __restrict__ hi, bf16* __restrict__ lo)
{
    long long i = ((long long)blockIdx.x * 256 + threadIdx.x) * 8;
    float4 a = *(const float4*)(in + i);
    float4 b = *(const float4*)(in + i + 4);
    float v[8] = {a.x, a.y, a.z, a.w, b.x, b.y, b.z, b.w};
    union { bf16 h[8]; uint4 u; } H, L;
    #pragma unroll
    for (int j = 0; j < 8; j++) split2(v[j], H.h[j], L.h[j]);
    *(uint4*)(hi + i) = H.u;
    *(uint4*)(lo + i) = L.u;
}

// ---------------------------------------------------------------------------
// Tiled transpose + split: in [R,C] fp32 -> out [C,R] bf16 hi/lo (per batch)
// Tile 64(R) x 32(C). Packed uint32 stores.
// ---------------------------------------------------------------------------
__global__ __launch_bounds__(256)
void split_trans(const float* __restrict__ in, bf16* __restrict__ hi, bf16* __restrict__ lo,
                 int R, int C)
{
    const int b = blockIdx.z;
    const long long n = (long long)R * C;
    in += b * n; hi += b * n; lo += b * n;
    const int r0 = blockIdx.y * 64, c0 = blockIdx.x * 32;
    __shared__ float t[32][65];
    const int lane = threadIdx.x & 31, w = threadIdx.x >> 5;
    #pragma unroll
    for (int i = 0; i < 8; i++) {
        int row = w * 8 + i;
        t[lane][row] = in[(long long)(r0 + row) * C + c0 + lane];
    }
    __syncthreads();
    #pragma unroll
    for (int p = 0; p < 4; p++) {
        int idx = threadIdx.x + p * 256;
        int c = idx >> 5;
        int rp = (idx & 31) * 2;
        bf16 h0, l0, h1, l1;
        split2(t[c][rp],     h0, l0);
        split2(t[c][rp + 1], h1, l1);
        long long off = (long long)(c0 + c) * R + r0 + rp;
        *(uint32_t*)(hi + off) = pack2b(h0, h1);
        *(uint32_t*)(lo + off) = pack2b(l0, l1);
    }
}

// ---------------------------------------------------------------------------
// Masked softmax over q (2048) per (b,v) row; emits bf16 hi/lo of attn too.
// Thread handles 8 contiguous q.
// ---------------------------------------------------------------------------
__global__ __launch_bounds__(256)
void softmax_mask(float* __restrict__ attn, const int* __restrict__ valid,
                  bf16* __restrict__ ahi, bf16* __restrict__ alo)
{
    const long long row = blockIdx.x;
    const int b = (int)(row / DVN);
    const int vl = valid[b];
    float* p = attn + row * (long long)LQN;
    const int tid = threadIdx.x;
    const int q0 = tid * 8;

    float v[8];
    {
        float4 a = *(const float4*)(p + q0);
        float4 c = *(const float4*)(p + q0 + 4);
        v[0]=a.x; v[1]=a.y; v[2]=a.z; v[3]=a.w;
        v[4]=c.x; v[5]=c.y; v[6]=c.z; v[7]=c.w;
    }
    float mx = -3.4e38f;
    #pragma unroll
    for (int i = 0; i < 8; i++) {
        v[i] = (q0 + i < vl) ? v[i] : -1000000.0f;
        mx = fmaxf(mx, v[i]);
    }
    __shared__ float red[256];
    red[tid] = mx; __syncthreads();
    for (int s = 128; s > 0; s >>= 1) { if (tid < s) red[tid] = fmaxf(red[tid], red[tid + s]); __syncthreads(); }
    mx = red[0]; __syncthreads();
    float sum = 0.0f;
    #pragma unroll
    for (int i = 0; i < 8; i++) { v[i] = expf(v[i] - mx); sum += v[i]; }
    red[tid] = sum; __syncthreads();
    for (int s = 128; s > 0; s >>= 1) { if (tid < s) red[tid] += red[tid + s]; __syncthreads(); }
    const float inv = 1.0f / red[0];

    union { bf16 h[8]; uint4 u; } H, L;
    #pragma unroll
    for (int i = 0; i < 8; i++) {
        v[i] *= inv;
        split2(v[i], H.h[i], L.h[i]);
    }
    *(float4*)(p + q0)     = make_float4(v[0], v[1], v[2], v[3]);
    *(float4*)(p + q0 + 4) = make_float4(v[4], v[5], v[6], v[7]);
    *(uint4*)(ahi + row * LQN + q0) = H.u;
    *(uint4*)(alo + row * LQN + q0) = L.u;
}

// ---------------------------------------------------------------------------
extern "C" void kernel_launch(void* const* d_in, const int* in_sizes, int n_in,
                              void* d_out, int out_size)
{
    const float* queries = (const float*)d_in[0];
    const float* keys    = (const float*)d_in[1];
    const float* values  = (const float*)d_in[2];
    const int*   valid   = (const int*)  d_in[3];
    const float* Wq      = (const float*)d_in[4];
    const float* Wk      = (const float*)d_in[5];
    const float* Wv      = (const float*)d_in[6];
    const float* Wo      = (const float*)d_in[7];

    float* out  = (float*)d_out;                         // [32,512,1024]
    float* attn = out + (size_t)BATCH * DVN * DIN;       // [32,512,2048]

    float *pk;
    bf16 *pUtH, *pUtL, *pWqH, *pWqL, *pGtH, *pGtL, *pqH, *pqL;
    bf16 *pvTH, *pvTL, *paH, *paL, *pTH, *pTL, *pWvTH, *pWvTL;
    cudaGetSymbolAddress((void**)&pk,   g_k);
    cudaGetSymbolAddress((void**)&pUtH, g_UtHi); cudaGetSymbolAddress((void**)&pUtL, g_UtLo);
    cudaGetSymbolAddress((void**)&pWqH, g_WqHi); cudaGetSymbolAddress((void**)&pWqL, g_WqLo);
    cudaGetSymbolAddress((void**)&pGtH, g_GtHi); cudaGetSymbolAddress((void**)&pGtL, g_GtLo);
    cudaGetSymbolAddress((void**)&pqH,  g_qHi);  cudaGetSymbolAddress((void**)&pqL,  g_qLo);
    cudaGetSymbolAddress((void**)&pvTH, g_vTHi); cudaGetSymbolAddress((void**)&pvTL, g_vTLo);
    cudaGetSymbolAddress((void**)&paH,  g_aHi);  cudaGetSymbolAddress((void**)&paL,  g_aLo);
    cudaGetSymbolAddress((void**)&pTH,  g_THi);  cudaGetSymbolAddress((void**)&pTL,  g_TLo);
    cudaGetSymbolAddress((void**)&pWvTH, g_WvTHi); cudaGetSymbolAddress((void**)&pWvTL, g_WvTLo);

    cudaFuncSetAttribute(mma_gemm<0>, cudaFuncAttributeMaxDynamicSharedMemorySize, MM_SMEM_TOTAL);
    cudaFuncSetAttribute(mma_gemm<1>, cudaFuncAttributeMaxDynamicSharedMemorySize, MM_SMEM_TOTAL);

    // K1: k = keys @ W_k (fp32 SIMT, small M=50)
    gemm128<<<dim3(DIN / 128, 1, BATCH), 256>>>(
        keys, Wk, pk, LKN, DIN, DIN,
        (long long)LKN * DIN, 0, (long long)LKN * DIN, DIN, DIN, DIN);

    // K2: Ut = (k^T @ W_o / 32)^T  -> bf16 hi/lo [B,512,1024]
    u_kernel<<<dim3(DVN / 32, DIN / 32, BATCH), 256>>>(pk, Wo, pUtH, pUtL);

    // Split Wq
    split_plain<<<(DIN * DIN) / 2048, 256>>>(Wq, pWqH, pWqL);

    // K3: Gt[v,i] = Ut[v,:] . Wq[i,:]   (M=512, N=1024, K=1024) -> bf16 split
    mma_gemm<1><<<dim3(DIN / 128, DVN / 128, BATCH), 256, MM_SMEM_TOTAL>>>(
        pUtH, pUtL, pWqH, pWqL, nullptr, pGtH, pGtL,
        DVN, DIN, DIN, (long long)DVN * DIN, 0, (long long)DVN * DIN, DIN);

    // Split queries
    split_plain<<<(int)(((long long)BATCH * LQN * DIN) / 2048), 256>>>(queries, pqH, pqL);

    // K4: scores[v,q] = Gt[v,:] . queries[q,:]  (M=512, N=2048, K=1024) -> fp32 attn buf
    mma_gemm<0><<<dim3(LQN / 128, DVN / 128, BATCH), 256, MM_SMEM_TOTAL>>>(
        pGtH, pGtL, pqH, pqL, attn, nullptr, nullptr,
        DVN, LQN, DIN, (long long)DVN * DIN, (long long)LQN * DIN, (long long)DVN * LQN, LQN);

    // K5: masked softmax over q (emits bf16 split of attn)
    softmax_mask<<<BATCH * DVN, 256>>>(attn, valid, paH, paL);

    // values -> transpose+split: vT [B,1024,2048]
    split_trans<<<dim3(DIN / 32, LQN / 64, BATCH), 256>>>(values, pvTH, pvTL, LQN, DIN);

    // K6: T[v,d] = attn[v,:] . vT[d,:]  (M=512, N=1024, K=2048) -> bf16 split
    mma_gemm<1><<<dim3(DIN / 128, DVN / 128, BATCH), 256, MM_SMEM_TOTAL>>>(
        paH, paL, pvTH, pvTL, nullptr, pTH, pTL,
        DVN, DIN, LQN, (long long)DVN * LQN, (long long)DIN * LQN, (long long)DVN * DIN, DIN);

    // Wv -> transpose+split: WvT [1024,1024]
    split_trans<<<dim3(DIN / 32, DIN / 64, 1), 256>>>(Wv, pWvTH, pWvTL, DIN, DIN);

    // K7: out[v,h] = T[v,:] . WvT[h,:]  (M=512, N=1024, K=1024) -> fp32 out
    mma_gemm<0><<<dim3(DIN / 128, DVN / 128, BATCH), 256, MM_SMEM_TOTAL>>>(
        pTH, pTL, pWvTH, pWvTL, out, nullptr, nullptr,
        DVN, DIN, DIN, (long long)DVN * DIN, 0, (long long)DVN * DIN, DIN);
}

// round 10
// speedup vs baseline: 1.5814x; 1.3073x over previous
#include <cuda_runtime.h>
#include <cuda_bf16.h>
#include <cstdint>

#define BATCH 32
#define LQN   2048
#define LKN   50
#define DIN   1024
#define DVN   512

typedef __nv_bfloat16 bf16;

// ---------------------------------------------------------------------------
// Scratch (device globals; allocations are forbidden)
// ---------------------------------------------------------------------------
__device__ float g_k[BATCH * LKN * DIN];                         // keys @ W_k (fp32)
__device__ bf16  g_UtHi[(size_t)BATCH * DVN * DIN];              // (k^T W_o /32)^T  [B,512,1024]
__device__ bf16  g_UtLo[(size_t)BATCH * DVN * DIN];
__device__ bf16  g_WqHi[DIN * DIN];
__device__ bf16  g_WqLo[DIN * DIN];
__device__ bf16  g_GtHi[(size_t)BATCH * DVN * DIN];              // G^T [B,512,1024]
__device__ bf16  g_GtLo[(size_t)BATCH * DVN * DIN];
__device__ bf16  g_qHi[(size_t)BATCH * LQN * DIN];               // queries split [B,2048,1024]
__device__ bf16  g_qLo[(size_t)BATCH * LQN * DIN];
__device__ bf16  g_vTHi[(size_t)BATCH * DIN * LQN];              // values^T split [B,1024,2048]
__device__ bf16  g_vTLo[(size_t)BATCH * DIN * LQN];
__device__ bf16  g_aHi[(size_t)BATCH * DVN * LQN];               // attn split [B,512,2048]
__device__ bf16  g_aLo[(size_t)BATCH * DVN * LQN];
__device__ bf16  g_THi[(size_t)BATCH * DVN * DIN];               // (attn@values) split [B,512,1024]
__device__ bf16  g_TLo[(size_t)BATCH * DVN * DIN];
__device__ bf16  g_WvTHi[DIN * DIN];                             // Wv^T split
__device__ bf16  g_WvTLo[DIN * DIN];

// ---------------------------------------------------------------------------
// Helpers
// ---------------------------------------------------------------------------
__device__ __forceinline__ uint32_t smem_u32(const void* p) {
    uint32_t a;
    asm("{ .reg .u64 t; cvta.to.shared.u64 t, %1; cvt.u32.u64 %0, t; }" : "=r"(a) : "l"(p));
    return a;
}
#define SW128(o) ((o) ^ (((o) >> 3) & 0x70))

__device__ __forceinline__ void cp16(uint32_t dst, const void* src) {
    asm volatile("cp.async.cg.shared.global [%0], [%1], 16;" :: "r"(dst), "l"(src) : "memory");
}
#define CP_COMMIT() asm volatile("cp.async.commit_group;" ::: "memory")
#define CP_WAIT0()  asm volatile("cp.async.wait_group 0;" ::: "memory")

__device__ __forceinline__ void ldsm4(uint32_t& r0, uint32_t& r1, uint32_t& r2, uint32_t& r3, uint32_t a) {
    asm volatile("ldmatrix.sync.aligned.m8n8.x4.shared.b16 {%0,%1,%2,%3}, [%4];"
                 : "=r"(r0), "=r"(r1), "=r"(r2), "=r"(r3) : "r"(a));
}
__device__ __forceinline__ void mma16816(float* d, const uint32_t* a, uint32_t b0, uint32_t b1) {
    asm volatile("mma.sync.aligned.m16n8k16.row.col.f32.bf16.bf16.f32 "
                 "{%0,%1,%2,%3},{%4,%5,%6,%7},{%8,%9},{%0,%1,%2,%3};"
                 : "+f"(d[0]), "+f"(d[1]), "+f"(d[2]), "+f"(d[3])
                 : "r"(a[0]), "r"(a[1]), "r"(a[2]), "r"(a[3]), "r"(b0), "r"(b1));
}
__device__ __forceinline__ void split2(float x, bf16& h, bf16& l) {
    h = __float2bfloat16(x);
    l = __float2bfloat16(x - __bfloat162float(h));
}
__device__ __forceinline__ uint32_t pack2b(bf16 a, bf16 b) {
    return ((uint32_t)__bfloat16_as_ushort(b) << 16) | __bfloat16_as_ushort(a);
}

// ---------------------------------------------------------------------------
// HMMA bf16-split GEMM:  C[b] = A[b] (MxK) @ B[b]^T  (B is [N,K] K-major)
// A,B as hi/lo bf16 pairs; 3-product split (hi*hi + lo*hi + hi*lo), fp32 acc.
// Block tile 128x128, 8 warps (4M x 2N), K-chunk 64, 2-stage cp.async,
// SW128 swizzle.  (Proven R4 core — inner loop untouched.)
// OUT_MODE 0: fp32 C.  OUT_MODE 1: bf16 hi/lo split C.
// SKIP_MODE 0: none. 1: skip CTA if bn >= valid[bz] (scores GEMM — masked q
//   columns are overwritten by softmax, never used). 2: limit K to
//   ceil(valid[bz]/64) chunks when valid>0 (attn columns beyond are exact 0).
// ---------------------------------------------------------------------------
#define STAGE_BYTES 65536        // Ahi,Alo,Bhi,Blo -- 4 x 16KB
#define MM_SMEM_TOTAL (2 * STAGE_BYTES)

template <int OUT_MODE, int SKIP_MODE>
__global__ __launch_bounds__(256, 1)
void mma_gemm(const bf16* __restrict__ Ahi, const bf16* __restrict__ Alo,
              const bf16* __restrict__ Bhi, const bf16* __restrict__ Blo,
              float* __restrict__ Cf, bf16* __restrict__ Chi, bf16* __restrict__ Clo,
              int M, int N, int K,
              long long sA, long long sB, long long sC, int ldc,
              const int* __restrict__ valid)
{
    extern __shared__ char smem[];
    const uint32_t sb = smem_u32(smem);
    const int tid = threadIdx.x;
    const int lane = tid & 31;
    const int wid = tid >> 5;
    const int warpM = wid & 3;
    const int warpN = wid >> 2;
    const int bz = blockIdx.z;
    const int bm = blockIdx.y * 128;
    const int bn = blockIdx.x * 128;

    int NC = K >> 6;
    if (SKIP_MODE == 1) {
        // scores GEMM: q-tiles at/after valid_len are dead (softmax masks them)
        if (bn >= valid[bz]) return;
    }
    if (SKIP_MODE == 2) {
        // attn@values: attn[:, q>=vl] == 0 exactly for vl>0
        int vl = valid[bz];
        if (vl > 0) { int nc2 = (vl + 63) >> 6; NC = nc2 < NC ? nc2 : NC; }
    }

    const char* gsrc[4];
    gsrc[0] = (const char*)(Ahi + (long long)bz * sA + (long long)bm * K);
    gsrc[1] = (const char*)(Alo + (long long)bz * sA + (long long)bm * K);
    gsrc[2] = (const char*)(Bhi + (long long)bz * sB + (long long)bn * K);
    gsrc[3] = (const char*)(Blo + (long long)bz * sB + (long long)bn * K);

    const int cr = tid >> 3;
    const int cs = (tid & 7) << 4;

    float acc[2][8][4];
    #pragma unroll
    for (int mt = 0; mt < 2; mt++)
        #pragma unroll
        for (int nt = 0; nt < 8; nt++)
            #pragma unroll
            for (int j = 0; j < 4; j++) acc[mt][nt][j] = 0.0f;

    const long long Kb = (long long)K * 2;

    {
        #pragma unroll
        for (int t = 0; t < 4; t++) {
            const char* s = gsrc[t];
            uint32_t d = sb + t * 16384;
            #pragma unroll
            for (int i = 0; i < 4; i++) {
                int r = cr + i * 32;
                cp16(d + SW128(r * 128 + cs), s + (long long)r * Kb + cs);
            }
        }
        CP_COMMIT();
    }

    const int mrowA = (lane & 7) + ((lane >> 3) & 1) * 8;
    const int kcA   = (lane >> 4) * 16;
    const int nrowB = (lane & 7) + ((lane >> 4) << 3);
    const int kcB   = ((lane >> 3) & 1) * 16;

    for (int c = 0; c < NC; c++) {
        CP_WAIT0();
        __syncthreads();

        if (c + 1 < NC) {
            const int k0b = (c + 1) << 7;
            uint32_t st = sb + ((c + 1) & 1) * STAGE_BYTES;
            #pragma unroll
            for (int t = 0; t < 4; t++) {
                const char* s = gsrc[t] + k0b;
                uint32_t d = st + t * 16384;
                #pragma unroll
                for (int i = 0; i < 4; i++) {
                    int r = cr + i * 32;
                    cp16(d + SW128(r * 128 + cs), s + (long long)r * Kb + cs);
                }
            }
            CP_COMMIT();
        }

        const uint32_t stg = sb + (c & 1) * STAGE_BYTES;
        const uint32_t bA0 = stg;
        const uint32_t bA1 = stg + 16384;
        const uint32_t bB0 = stg + 32768;
        const uint32_t bB1 = stg + 49152;

        #pragma unroll
        for (int ks = 0; ks < 4; ks++) {
            uint32_t ah[2][4], al[2][4];
            #pragma unroll
            for (int mt = 0; mt < 2; mt++) {
                uint32_t off = SW128((warpM * 32 + mt * 16 + mrowA) * 128 + ks * 32 + kcA);
                ldsm4(ah[mt][0], ah[mt][1], ah[mt][2], ah[mt][3], bA0 + off);
                ldsm4(al[mt][0], al[mt][1], al[mt][2], al[mt][3], bA1 + off);
            }
            uint32_t bh[8][2], bl[8][2];
            #pragma unroll
            for (int np = 0; np < 4; np++) {
                uint32_t off = SW128((warpN * 64 + np * 16 + nrowB) * 128 + ks * 32 + kcB);
                ldsm4(bh[2*np][0], bh[2*np][1], bh[2*np+1][0], bh[2*np+1][1], bB0 + off);
                ldsm4(bl[2*np][0], bl[2*np][1], bl[2*np+1][0], bl[2*np+1][1], bB1 + off);
            }
            #pragma unroll
            for (int mt = 0; mt < 2; mt++)
                #pragma unroll
                for (int nt = 0; nt < 8; nt++) {
                    mma16816(acc[mt][nt], ah[mt], bh[nt][0], bh[nt][1]);
                    mma16816(acc[mt][nt], al[mt], bh[nt][0], bh[nt][1]);
                    mma16816(acc[mt][nt], ah[mt], bl[nt][0], bl[nt][1]);
                }
        }
        __syncthreads();
    }

    const long long cbase = (long long)bz * sC;
    #pragma unroll
    for (int mt = 0; mt < 2; mt++) {
        const int r0 = bm + warpM * 32 + mt * 16 + (lane >> 2);
        #pragma unroll
        for (int half = 0; half < 2; half++) {
            const int r = r0 + half * 8;
            const long long rowoff = cbase + (long long)r * ldc + bn + warpN * 64 + (lane & 3) * 2;
            #pragma unroll
            for (int nt = 0; nt < 8; nt++) {
                float x0 = acc[mt][nt][half * 2 + 0];
                float x1 = acc[mt][nt][half * 2 + 1];
                long long off = rowoff + nt * 8;
                if (OUT_MODE == 0) {
                    *(float2*)(Cf + off) = make_float2(x0, x1);
                } else {
                    bf16 sh0, sl0, sh1, sl1;
                    split2(x0, sh0, sl0);
                    split2(x1, sh1, sl1);
                    *(uint32_t*)(Chi + off) = pack2b(sh0, sh1);
                    *(uint32_t*)(Clo + off) = pack2b(sl0, sl1);
                }
            }
        }
    }
}

// ---------------------------------------------------------------------------
// fp32 SIMT GEMM for the small K-projection (M=50): C = A(MxK) @ B(KxN)
// ---------------------------------------------------------------------------
__global__ __launch_bounds__(256)
void gemm128(const float* __restrict__ A, const float* __restrict__ Bm,
             float* __restrict__ C, int M, int N, int K,
             long long sA, long long sB, long long sC, int lda, int ldb, int ldc)
{
    const int b = blockIdx.z;
    A += (long long)b * sA; Bm += (long long)b * sB; C += (long long)b * sC;
    const int bm = blockIdx.y * 128, bn = blockIdx.x * 128;
    __shared__ float As[16][128], Bs[16][128];
    const int tid = threadIdx.x, tx = tid & 15, ty = tid >> 4;
    float acc[8][8];
    #pragma unroll
    for (int i = 0; i < 8; i++)
        #pragma unroll
        for (int j = 0; j < 8; j++) acc[i][j] = 0.0f;

    for (int k0 = 0; k0 < K; k0 += 16) {
        #pragma unroll
        for (int l = 0; l < 2; l++) {
            int t = tid + l * 256, row = t >> 2, col = (t & 3) << 2;
            float4 v = make_float4(0.f, 0.f, 0.f, 0.f);
            if (bm + row < M) v = *(const float4*)(A + (long long)(bm + row) * lda + k0 + col);
            As[col + 0][row] = v.x; As[col + 1][row] = v.y;
            As[col + 2][row] = v.z; As[col + 3][row] = v.w;
        }
        #pragma unroll
        for (int l = 0; l < 2; l++) {
            int t = tid + l * 256, row = t >> 5, col = (t & 31) << 2;
            *(float4*)&Bs[row][col] = *(const float4*)(Bm + (long long)(k0 + row) * ldb + bn + col);
        }
        __syncthreads();
        #pragma unroll
        for (int kk = 0; kk < 16; kk++) {
            float a[8], bb[8];
            float4 a0 = *(const float4*)&As[kk][ty * 8];
            float4 a1 = *(const float4*)&As[kk][ty * 8 + 4];
            a[0]=a0.x; a[1]=a0.y; a[2]=a0.z; a[3]=a0.w; a[4]=a1.x; a[5]=a1.y; a[6]=a1.z; a[7]=a1.w;
            float4 b0 = *(const float4*)&Bs[kk][tx * 8];
            float4 b1 = *(const float4*)&Bs[kk][tx * 8 + 4];
            bb[0]=b0.x; bb[1]=b0.y; bb[2]=b0.z; bb[3]=b0.w; bb[4]=b1.x; bb[5]=b1.y; bb[6]=b1.z; bb[7]=b1.w;
            #pragma unroll
            for (int i = 0; i < 8; i++)
                #pragma unroll
                for (int j = 0; j < 8; j++) acc[i][j] = fmaf(a[i], bb[j], acc[i][j]);
        }
        __syncthreads();
    }
    #pragma unroll
    for (int i = 0; i < 8; i++) {
        int m = bm + ty * 8 + i;
        if (m >= M) continue;
        #pragma unroll
        for (int j = 0; j < 8; j++) C[(long long)m * ldc + bn + tx * 8 + j] = acc[i][j];
    }
}

// ---------------------------------------------------------------------------
// Ut[b,v,h] = (1/32) * sum_k (keys@Wk)[b,k,h] * Wo[k,v] -> bf16 hi/lo, packed
// ---------------------------------------------------------------------------
__global__ __launch_bounds__(256)
void u_kernel(const float* __restrict__ kmat, const float* __restrict__ Wo,
              bf16* __restrict__ uhi, bf16* __restrict__ ulo)
{
    const int b = blockIdx.z, hb = blockIdx.y * 32, v0 = blockIdx.x * 32;
    __shared__ float ks[LKN][32], wo[LKN][32];
    const int tid = threadIdx.x;
    for (int i = tid; i < LKN * 32; i += 256) {
        int kk = i >> 5, c = i & 31;
        ks[kk][c] = kmat[((long long)b * LKN + kk) * DIN + hb + c];
        wo[kk][c] = Wo[kk * DVN + v0 + c];
    }
    __syncthreads();
    const int hp = (tid & 15) * 2;
    const int vi = tid >> 4;
    float a00 = 0.f, a01 = 0.f, a10 = 0.f, a11 = 0.f;
    for (int kk = 0; kk < LKN; kk++) {
        float k0 = ks[kk][hp], k1 = ks[kk][hp + 1];
        float w0 = wo[kk][vi], w1 = wo[kk][vi + 16];
        a00 = fmaf(k0, w0, a00); a01 = fmaf(k1, w0, a01);
        a10 = fmaf(k0, w1, a10); a11 = fmaf(k1, w1, a11);
    }
    const float s = 0.03125f;
    #pragma unroll
    for (int sv = 0; sv < 2; sv++) {
        float x0 = (sv ? a10 : a00) * s;
        float x1 = (sv ? a11 : a01) * s;
        bf16 sh0, sl0, sh1, sl1;
        split2(x0, sh0, sl0);
        split2(x1, sh1, sl1);
        long long off = ((long long)b * DVN + v0 + vi + sv * 16) * DIN + hb + hp;
        *(uint32_t*)(uhi + off) = pack2b(sh0, sh1);
        *(uint32_t*)(ulo + off) = pack2b(sl0, sl1);
    }
}

// ---------------------------------------------------------------------------
// Elementwise fp32 -> bf16 hi/lo (n multiple of 2048); uint4 stores
// ---------------------------------------------------------------------------
__global__ __launch_bounds__(256)
void split_plain(const float* __restrict__ in, bf16* __restrict__ hi, bf16* __restrict__ lo)
{
    long long i = ((long long)blockIdx.x * 256 + threadIdx.x) * 8;
    float4 a = *(const float4*)(in + i);
    float4 b = *(const float4*)(in + i + 4);
    float v[8] = {a.x, a.y, a.z, a.w, b.x, b.y, b.z, b.w};
    union { bf16 h[8]; uint4 u; } H, L;
    #pragma unroll
    for (int j = 0; j < 8; j++) split2(v[j], H.h[j], L.h[j]);
    *(uint4*)(hi + i) = H.u;
    *(uint4*)(lo + i) = L.u;
}

// ---------------------------------------------------------------------------
// queries split with valid_len skip: rows q >= valid[b] are never read by the
// scores GEMM (its N-tiles there are skipped). Block = 2 q-rows of one batch.
// ---------------------------------------------------------------------------
__global__ __launch_bounds__(256)
void split_q(const float* __restrict__ in, bf16* __restrict__ hi, bf16* __restrict__ lo,
             const int* __restrict__ valid)
{
    const int b = blockIdx.x >> 10;               // LQN/2 = 1024 row-pairs per batch
    const int q0 = (blockIdx.x & 1023) * 2;
    if (q0 >= valid[b]) return;
    long long base = ((long long)b * LQN + q0) * DIN;
    long long i = base + (long long)threadIdx.x * 8;
    float4 a = *(const float4*)(in + i);
    float4 c = *(const float4*)(in + i + 4);
    float v[8] = {a.x, a.y, a.z, a.w, c.x, c.y, c.z, c.w};
    union { bf16 h[8]; uint4 u; } H, L;
    #pragma unroll
    for (int j = 0; j < 8; j++) split2(v[j], H.h[j], L.h[j]);
    *(uint4*)(hi + i) = H.u;
    *(uint4*)(lo + i) = L.u;
}

// ---------------------------------------------------------------------------
// Tiled transpose + split: in [R,C] fp32 -> out [C,R] bf16 hi/lo (per batch)
// Tile 64(R) x 32(C). Optional valid: skip R-tiles beyond valid_len (vl>0).
// ---------------------------------------------------------------------------
__global__ __launch_bounds__(256)
void split_trans(const float* __restrict__ in, bf16* __restrict__ hi, bf16* __restrict__ lo,
                 int R, int C, const int* __restrict__ valid)
{
    const int b = blockIdx.z;
    const int r0 = blockIdx.y * 64, c0 = blockIdx.x * 32;
    if (valid) {
        int vl = valid[b];
        if (vl > 0 && r0 >= vl) return;      // vl==0: attn uniform, full K needed
    }
    const long long n = (long long)R * C;
    in += b * n; hi += b * n; lo += b * n;
    __shared__ float t[32][65];
    const int lane = threadIdx.x & 31, w = threadIdx.x >> 5;
    #pragma unroll
    for (int i = 0; i < 8; i++) {
        int row = w * 8 + i;
        t[lane][row] = in[(long long)(r0 + row) * C + c0 + lane];
    }
    __syncthreads();
    #pragma unroll
    for (int p = 0; p < 4; p++) {
        int idx = threadIdx.x + p * 256;
        int c = idx >> 5;
        int rp = (idx & 31) * 2;
        bf16 h0, l0, h1, l1;
        split2(t[c][rp],     h0, l0);
        split2(t[c][rp + 1], h1, l1);
        long long off = (long long)(c0 + c) * R + r0 + rp;
        *(uint32_t*)(hi + off) = pack2b(h0, h1);
        *(uint32_t*)(lo + off) = pack2b(l0, l1);
    }
}

// ---------------------------------------------------------------------------
// Masked softmax over q (2048) per (b,v) row; emits bf16 hi/lo of attn too.
// Masked positions (q >= vl, vl>0) produce exact 0 (exp underflow), matching
// the fp32 reference. Skipped score tiles leave garbage that is masked here.
// ---------------------------------------------------------------------------
__global__ __launch_bounds__(256)
void softmax_mask(float* __restrict__ attn, const int* __restrict__ valid,
                  bf16* __restrict__ ahi, bf16* __restrict__ alo)
{
    const long long row = blockIdx.x;
    const int b = (int)(row / DVN);
    const int vl = valid[b];
    float* p = attn + row * (long long)LQN;
    const int tid = threadIdx.x;
    const int q0 = tid * 8;

    float v[8];
    {
        float4 a = *(const float4*)(p + q0);
        float4 c = *(const float4*)(p + q0 + 4);
        v[0]=a.x; v[1]=a.y; v[2]=a.z; v[3]=a.w;
        v[4]=c.x; v[5]=c.y; v[6]=c.z; v[7]=c.w;
    }
    float mx = -3.4e38f;
    #pragma unroll
    for (int i = 0; i < 8; i++) {
        v[i] = (q0 + i < vl) ? v[i] : -1000000.0f;
        mx = fmaxf(mx, v[i]);
    }
    __shared__ float red[256];
    red[tid] = mx; __syncthreads();
    for (int s = 128; s > 0; s >>= 1) { if (tid < s) red[tid] = fmaxf(red[tid], red[tid + s]); __syncthreads(); }
    mx = red[0]; __syncthreads();
    float sum = 0.0f;
    #pragma unroll
    for (int i = 0; i < 8; i++) { v[i] = expf(v[i] - mx); sum += v[i]; }
    red[tid] = sum; __syncthreads();
    for (int s = 128; s > 0; s >>= 1) { if (tid < s) red[tid] += red[tid + s]; __syncthreads(); }
    const float inv = 1.0f / red[0];

    union { bf16 h[8]; uint4 u; } H, L;
    #pragma unroll
    for (int i = 0; i < 8; i++) {
        v[i] *= inv;
        split2(v[i], H.h[i], L.h[i]);
    }
    *(float4*)(p + q0)     = make_float4(v[0], v[1], v[2], v[3]);
    *(float4*)(p + q0 + 4) = make_float4(v[4], v[5], v[6], v[7]);
    *(uint4*)(ahi + row * LQN + q0) = H.u;
    *(uint4*)(alo + row * LQN + q0) = L.u;
}

// ---------------------------------------------------------------------------
extern "C" void kernel_launch(void* const* d_in, const int* in_sizes, int n_in,
                              void* d_out, int out_size)
{
    const float* queries = (const float*)d_in[0];
    const float* keys    = (const float*)d_in[1];
    const float* values  = (const float*)d_in[2];
    const int*   valid   = (const int*)  d_in[3];
    const float* Wq      = (const float*)d_in[4];
    const float* Wk      = (const float*)d_in[5];
    const float* Wv      = (const float*)d_in[6];
    const float* Wo      = (const float*)d_in[7];

    float* out  = (float*)d_out;                         // [32,512,1024]
    float* attn = out + (size_t)BATCH * DVN * DIN;       // [32,512,2048]

    float *pk;
    bf16 *pUtH, *pUtL, *pWqH, *pWqL, *pGtH, *pGtL, *pqH, *pqL;
    bf16 *pvTH, *pvTL, *paH, *paL, *pTH, *pTL, *pWvTH, *pWvTL;
    cudaGetSymbolAddress((void**)&pk,   g_k);
    cudaGetSymbolAddress((void**)&pUtH, g_UtHi); cudaGetSymbolAddress((void**)&pUtL, g_UtLo);
    cudaGetSymbolAddress((void**)&pWqH, g_WqHi); cudaGetSymbolAddress((void**)&pWqL, g_WqLo);
    cudaGetSymbolAddress((void**)&pGtH, g_GtHi); cudaGetSymbolAddress((void**)&pGtL, g_GtLo);
    cudaGetSymbolAddress((void**)&pqH,  g_qHi);  cudaGetSymbolAddress((void**)&pqL,  g_qLo);
    cudaGetSymbolAddress((void**)&pvTH, g_vTHi); cudaGetSymbolAddress((void**)&pvTL, g_vTLo);
    cudaGetSymbolAddress((void**)&paH,  g_aHi);  cudaGetSymbolAddress((void**)&paL,  g_aLo);
    cudaGetSymbolAddress((void**)&pTH,  g_THi);  cudaGetSymbolAddress((void**)&pTL,  g_TLo);
    cudaGetSymbolAddress((void**)&pWvTH, g_WvTHi); cudaGetSymbolAddress((void**)&pWvTL, g_WvTLo);

    cudaFuncSetAttribute(mma_gemm<0,0>, cudaFuncAttributeMaxDynamicSharedMemorySize, MM_SMEM_TOTAL);
    cudaFuncSetAttribute(mma_gemm<1,0>, cudaFuncAttributeMaxDynamicSharedMemorySize, MM_SMEM_TOTAL);
    cudaFuncSetAttribute(mma_gemm<0,1>, cudaFuncAttributeMaxDynamicSharedMemorySize, MM_SMEM_TOTAL);
    cudaFuncSetAttribute(mma_gemm<1,2>, cudaFuncAttributeMaxDynamicSharedMemorySize, MM_SMEM_TOTAL);

    // K1: k = keys @ W_k (fp32 SIMT, small M=50)
    gemm128<<<dim3(DIN / 128, 1, BATCH), 256>>>(
        keys, Wk, pk, LKN, DIN, DIN,
        (long long)LKN * DIN, 0, (long long)LKN * DIN, DIN, DIN, DIN);

    // K2: Ut = (k^T @ W_o / 32)^T  -> bf16 hi/lo [B,512,1024]
    u_kernel<<<dim3(DVN / 32, DIN / 32, BATCH), 256>>>(pk, Wo, pUtH, pUtL);

    // Split Wq
    split_plain<<<(DIN * DIN) / 2048, 256>>>(Wq, pWqH, pWqL);

    // K3: Gt[v,i] = Ut[v,:] . Wq[i,:]   (M=512, N=1024, K=1024) -> bf16 split
    mma_gemm<1,0><<<dim3(DIN / 128, DVN / 128, BATCH), 256, MM_SMEM_TOTAL>>>(
        pUtH, pUtL, pWqH, pWqL, nullptr, pGtH, pGtL,
        DVN, DIN, DIN, (long long)DVN * DIN, 0, (long long)DVN * DIN, DIN, nullptr);

    // Split queries (skip rows beyond valid_len — never read by K4)
    split_q<<<BATCH * (LQN / 2), 256>>>(queries, pqH, pqL, valid);

    // K4: scores[v,q] = Gt[v,:] . queries[q,:]  (skip q-tiles >= valid_len)
    mma_gemm<0,1><<<dim3(LQN / 128, DVN / 128, BATCH), 256, MM_SMEM_TOTAL>>>(
        pGtH, pGtL, pqH, pqL, attn, nullptr, nullptr,
        DVN, LQN, DIN, (long long)DVN * DIN, (long long)LQN * DIN, (long long)DVN * LQN, LQN, valid);

    // K5: masked softmax over q (emits bf16 split of attn)
    softmax_mask<<<BATCH * DVN, 256>>>(attn, valid, paH, paL);

    // values -> transpose+split (skip q-tiles beyond valid_len when vl>0)
    split_trans<<<dim3(DIN / 32, LQN / 64, BATCH), 256>>>(values, pvTH, pvTL, LQN, DIN, valid);

    // K6: T[v,d] = attn[v,:] . vT[d,:]  (K limited to ceil(vl/64) chunks)
    mma_gemm<1,2><<<dim3(DIN / 128, DVN / 128, BATCH), 256, MM_SMEM_TOTAL>>>(
        paH, paL, pvTH, pvTL, nullptr, pTH, pTL,
        DVN, DIN, LQN, (long long)DVN * LQN, (long long)DIN * LQN, (long long)DVN * DIN, DIN, valid);

    // Wv -> transpose+split: WvT [1024,1024]
    split_trans<<<dim3(DIN / 32, DIN / 64, 1), 256>>>(Wv, pWvTH, pWvTL, DIN, DIN, nullptr);

    // K7: out[v,h] = T[v,:] . WvT[h,:]  (M=512, N=1024, K=1024) -> fp32 out
    mma_gemm<0,0><<<dim3(DIN / 128, DVN / 128, BATCH), 256, MM_SMEM_TOTAL>>>(
        pTH, pTL, pWvTH, pWvTL, out, nullptr, nullptr,
        DVN, DIN, DIN, (long long)DVN * DIN, 0, (long long)DVN * DIN, DIN, nullptr);
}

// round 12
// speedup vs baseline: 2.1721x; 1.3735x over previous
#include <cuda_runtime.h>
#include <cuda_bf16.h>
#include <cstdint>

#define BATCH 32
#define LQN   2048
#define LKN   50
#define DIN   1024
#define DVN   512

typedef __nv_bfloat16 bf16;

// ---------------------------------------------------------------------------
// Scratch (device globals; allocations are forbidden)
// ---------------------------------------------------------------------------
__device__ float g_k[BATCH * LKN * DIN];                         // keys @ W_k (fp32)
__device__ bf16  g_kHi[(size_t)BATCH * 128 * DIN];               // k padded to 128 rows, split
__device__ bf16  g_kLo[(size_t)BATCH * 128 * DIN];
__device__ bf16  g_WqHi[DIN * DIN];
__device__ bf16  g_WqLo[DIN * DIN];
__device__ bf16  g_ZHi[(size_t)BATCH * 128 * DIN];               // Z = k_pad @ Wq^T, split
__device__ bf16  g_ZLo[(size_t)BATCH * 128 * DIN];
__device__ float g_P[(size_t)BATCH * LQN * 128];                 // P = queries @ Z^T (fp32)
__device__ bf16  g_qHi[(size_t)BATCH * LQN * DIN];               // queries split [B,2048,1024]
__device__ bf16  g_qLo[(size_t)BATCH * LQN * DIN];
__device__ bf16  g_vTHi[(size_t)BATCH * DIN * LQN];              // values^T split [B,1024,2048]
__device__ bf16  g_vTLo[(size_t)BATCH * DIN * LQN];
__device__ bf16  g_aHi[(size_t)BATCH * DVN * LQN];               // attn split [B,512,2048]
__device__ bf16  g_aLo[(size_t)BATCH * DVN * LQN];
__device__ bf16  g_THi[(size_t)BATCH * DVN * DIN];               // (attn@values) split [B,512,1024]
__device__ bf16  g_TLo[(size_t)BATCH * DVN * DIN];
__device__ bf16  g_WvTHi[DIN * DIN];                             // Wv^T split
__device__ bf16  g_WvTLo[DIN * DIN];

// ---------------------------------------------------------------------------
// Helpers
// ---------------------------------------------------------------------------
__device__ __forceinline__ uint32_t smem_u32(const void* p) {
    uint32_t a;
    asm("{ .reg .u64 t; cvta.to.shared.u64 t, %1; cvt.u32.u64 %0, t; }" : "=r"(a) : "l"(p));
    return a;
}
#define SW128(o) ((o) ^ (((o) >> 3) & 0x70))

__device__ __forceinline__ void cp16(uint32_t dst, const void* src) {
    asm volatile("cp.async.cg.shared.global [%0], [%1], 16;" :: "r"(dst), "l"(src) : "memory");
}
#define CP_COMMIT() asm volatile("cp.async.commit_group;" ::: "memory")
#define CP_WAIT0()  asm volatile("cp.async.wait_group 0;" ::: "memory")

__device__ __forceinline__ void ldsm4(uint32_t& r0, uint32_t& r1, uint32_t& r2, uint32_t& r3, uint32_t a) {
    asm volatile("ldmatrix.sync.aligned.m8n8.x4.shared.b16 {%0,%1,%2,%3}, [%4];"
                 : "=r"(r0), "=r"(r1), "=r"(r2), "=r"(r3) : "r"(a));
}
__device__ __forceinline__ void mma16816(float* d, const uint32_t* a, uint32_t b0, uint32_t b1) {
    asm volatile("mma.sync.aligned.m16n8k16.row.col.f32.bf16.bf16.f32 "
                 "{%0,%1,%2,%3},{%4,%5,%6,%7},{%8,%9},{%0,%1,%2,%3};"
                 : "+f"(d[0]), "+f"(d[1]), "+f"(d[2]), "+f"(d[3])
                 : "r"(a[0]), "r"(a[1]), "r"(a[2]), "r"(a[3]), "r"(b0), "r"(b1));
}
__device__ __forceinline__ void split2(float x, bf16& h, bf16& l) {
    h = __float2bfloat16(x);
    l = __float2bfloat16(x - __bfloat162float(h));
}
__device__ __forceinline__ uint32_t pack2b(bf16 a, bf16 b) {
    return ((uint32_t)__bfloat16_as_ushort(b) << 16) | __bfloat16_as_ushort(a);
}

// ---------------------------------------------------------------------------
// HMMA bf16-split GEMM:  C[b] = A[b] (MxK) @ B[b]^T  (B is [N,K] K-major)
// A,B as hi/lo bf16 pairs; 3-product split, fp32 acc. Proven R4 core.
// OUT_MODE 0: fp32 C.  OUT_MODE 1: bf16 hi/lo split C.
// SKIP_MODE 0: none. 1: skip CTA if bn >= valid[bz]. 2: limit K to
//   ceil(valid[bz]/64) chunks when valid>0. 3: skip CTA if bm >= valid[bz].
// ---------------------------------------------------------------------------
#define STAGE_BYTES 65536        // Ahi,Alo,Bhi,Blo -- 4 x 16KB
#define MM_SMEM_TOTAL (2 * STAGE_BYTES)

template <int OUT_MODE, int SKIP_MODE>
__global__ __launch_bounds__(256, 1)
void mma_gemm(const bf16* __restrict__ Ahi, const bf16* __restrict__ Alo,
              const bf16* __restrict__ Bhi, const bf16* __restrict__ Blo,
              float* __restrict__ Cf, bf16* __restrict__ Chi, bf16* __restrict__ Clo,
              int M, int N, int K,
              long long sA, long long sB, long long sC, int ldc,
              const int* __restrict__ valid)
{
    extern __shared__ char smem[];
    const uint32_t sb = smem_u32(smem);
    const int tid = threadIdx.x;
    const int lane = tid & 31;
    const int wid = tid >> 5;
    const int warpM = wid & 3;
    const int warpN = wid >> 2;
    const int bz = blockIdx.z;
    const int bm = blockIdx.y * 128;
    const int bn = blockIdx.x * 128;

    int NC = K >> 6;
    if (SKIP_MODE == 1) { if (bn >= valid[bz]) return; }
    if (SKIP_MODE == 3) { if (bm >= valid[bz]) return; }
    if (SKIP_MODE == 2) {
        int vl = valid[bz];
        if (vl > 0) { int nc2 = (vl + 63) >> 6; NC = nc2 < NC ? nc2 : NC; }
    }

    const char* gsrc[4];
    gsrc[0] = (const char*)(Ahi + (long long)bz * sA + (long long)bm * K);
    gsrc[1] = (const char*)(Alo + (long long)bz * sA + (long long)bm * K);
    gsrc[2] = (const char*)(Bhi + (long long)bz * sB + (long long)bn * K);
    gsrc[3] = (const char*)(Blo + (long long)bz * sB + (long long)bn * K);

    const int cr = tid >> 3;
    const int cs = (tid & 7) << 4;

    float acc[2][8][4];
    #pragma unroll
    for (int mt = 0; mt < 2; mt++)
        #pragma unroll
        for (int nt = 0; nt < 8; nt++)
            #pragma unroll
            for (int j = 0; j < 4; j++) acc[mt][nt][j] = 0.0f;

    const long long Kb = (long long)K * 2;

    {
        #pragma unroll
        for (int t = 0; t < 4; t++) {
            const char* s = gsrc[t];
            uint32_t d = sb + t * 16384;
            #pragma unroll
            for (int i = 0; i < 4; i++) {
                int r = cr + i * 32;
                cp16(d + SW128(r * 128 + cs), s + (long long)r * Kb + cs);
            }
        }
        CP_COMMIT();
    }

    const int mrowA = (lane & 7) + ((lane >> 3) & 1) * 8;
    const int kcA   = (lane >> 4) * 16;
    const int nrowB = (lane & 7) + ((lane >> 4) << 3);
    const int kcB   = ((lane >> 3) & 1) * 16;

    for (int c = 0; c < NC; c++) {
        CP_WAIT0();
        __syncthreads();

        if (c + 1 < NC) {
            const int k0b = (c + 1) << 7;
            uint32_t st = sb + ((c + 1) & 1) * STAGE_BYTES;
            #pragma unroll
            for (int t = 0; t < 4; t++) {
                const char* s = gsrc[t] + k0b;
                uint32_t d = st + t * 16384;
                #pragma unroll
                for (int i = 0; i < 4; i++) {
                    int r = cr + i * 32;
                    cp16(d + SW128(r * 128 + cs), s + (long long)r * Kb + cs);
                }
            }
            CP_COMMIT();
        }

        const uint32_t stg = sb + (c & 1) * STAGE_BYTES;
        const uint32_t bA0 = stg;
        const uint32_t bA1 = stg + 16384;
        const uint32_t bB0 = stg + 32768;
        const uint32_t bB1 = stg + 49152;

        #pragma unroll
        for (int ks = 0; ks < 4; ks++) {
            uint32_t ah[2][4], al[2][4];
            #pragma unroll
            for (int mt = 0; mt < 2; mt++) {
                uint32_t off = SW128((warpM * 32 + mt * 16 + mrowA) * 128 + ks * 32 + kcA);
                ldsm4(ah[mt][0], ah[mt][1], ah[mt][2], ah[mt][3], bA0 + off);
                ldsm4(al[mt][0], al[mt][1], al[mt][2], al[mt][3], bA1 + off);
            }
            uint32_t bh[8][2], bl[8][2];
            #pragma unroll
            for (int np = 0; np < 4; np++) {
                uint32_t off = SW128((warpN * 64 + np * 16 + nrowB) * 128 + ks * 32 + kcB);
                ldsm4(bh[2*np][0], bh[2*np][1], bh[2*np+1][0], bh[2*np+1][1], bB0 + off);
                ldsm4(bl[2*np][0], bl[2*np][1], bl[2*np+1][0], bl[2*np+1][1], bB1 + off);
            }
            #pragma unroll
            for (int mt = 0; mt < 2; mt++)
                #pragma unroll
                for (int nt = 0; nt < 8; nt++) {
                    mma16816(acc[mt][nt], ah[mt], bh[nt][0], bh[nt][1]);
                    mma16816(acc[mt][nt], al[mt], bh[nt][0], bh[nt][1]);
                    mma16816(acc[mt][nt], ah[mt], bl[nt][0], bl[nt][1]);
                }
        }
        __syncthreads();
    }

    const long long cbase = (long long)bz * sC;
    #pragma unroll
    for (int mt = 0; mt < 2; mt++) {
        const int r0 = bm + warpM * 32 + mt * 16 + (lane >> 2);
        #pragma unroll
        for (int half = 0; half < 2; half++) {
            const int r = r0 + half * 8;
            const long long rowoff = cbase + (long long)r * ldc + bn + warpN * 64 + (lane & 3) * 2;
            #pragma unroll
            for (int nt = 0; nt < 8; nt++) {
                float x0 = acc[mt][nt][half * 2 + 0];
                float x1 = acc[mt][nt][half * 2 + 1];
                long long off = rowoff + nt * 8;
                if (OUT_MODE == 0) {
                    *(float2*)(Cf + off) = make_float2(x0, x1);
                } else {
                    bf16 sh0, sl0, sh1, sl1;
                    split2(x0, sh0, sl0);
                    split2(x1, sh1, sl1);
                    *(uint32_t*)(Chi + off) = pack2b(sh0, sh1);
                    *(uint32_t*)(Clo + off) = pack2b(sl0, sl1);
                }
            }
        }
    }
}

// ---------------------------------------------------------------------------
// fp32 SIMT GEMM for the small K-projection (M=50): C = A(MxK) @ B(KxN)
// ---------------------------------------------------------------------------
__global__ __launch_bounds__(256)
void gemm128(const float* __restrict__ A, const float* __restrict__ Bm,
             float* __restrict__ C, int M, int N, int K,
             long long sA, long long sB, long long sC, int lda, int ldb, int ldc)
{
    const int b = blockIdx.z;
    A += (long long)b * sA; Bm += (long long)b * sB; C += (long long)b * sC;
    const int bm = blockIdx.y * 128, bn = blockIdx.x * 128;
    __shared__ float As[16][128], Bs[16][128];
    const int tid = threadIdx.x, tx = tid & 15, ty = tid >> 4;
    float acc[8][8];
    #pragma unroll
    for (int i = 0; i < 8; i++)
        #pragma unroll
        for (int j = 0; j < 8; j++) acc[i][j] = 0.0f;

    for (int k0 = 0; k0 < K; k0 += 16) {
        #pragma unroll
        for (int l = 0; l < 2; l++) {
            int t = tid + l * 256, row = t >> 2, col = (t & 3) << 2;
            float4 v = make_float4(0.f, 0.f, 0.f, 0.f);
            if (bm + row < M) v = *(const float4*)(A + (long long)(bm + row) * lda + k0 + col);
            As[col + 0][row] = v.x; As[col + 1][row] = v.y;
            As[col + 2][row] = v.z; As[col + 3][row] = v.w;
        }
        #pragma unroll
        for (int l = 0; l < 2; l++) {
            int t = tid + l * 256, row = t >> 5, col = (t & 31) << 2;
            *(float4*)&Bs[row][col] = *(const float4*)(Bm + (long long)(k0 + row) * ldb + bn + col);
        }
        __syncthreads();
        #pragma unroll
        for (int kk = 0; kk < 16; kk++) {
            float a[8], bb[8];
            float4 a0 = *(const float4*)&As[kk][ty * 8];
            float4 a1 = *(const float4*)&As[kk][ty * 8 + 4];
            a[0]=a0.x; a[1]=a0.y; a[2]=a0.z; a[3]=a0.w; a[4]=a1.x; a[5]=a1.y; a[6]=a1.z; a[7]=a1.w;
            float4 b0 = *(const float4*)&Bs[kk][tx * 8];
            float4 b1 = *(const float4*)&Bs[kk][tx * 8 + 4];
            bb[0]=b0.x; bb[1]=b0.y; bb[2]=b0.z; bb[3]=b0.w; bb[4]=b1.x; bb[5]=b1.y; bb[6]=b1.z; bb[7]=b1.w;
            #pragma unroll
            for (int i = 0; i < 8; i++)
                #pragma unroll
                for (int j = 0; j < 8; j++) acc[i][j] = fmaf(a[i], bb[j], acc[i][j]);
        }
        __syncthreads();
    }
    #pragma unroll
    for (int i = 0; i < 8; i++) {
        int m = bm + ty * 8 + i;
        if (m >= M) continue;
        #pragma unroll
        for (int j = 0; j < 8; j++) C[(long long)m * ldc + bn + tx * 8 + j] = acc[i][j];
    }
}

// ---------------------------------------------------------------------------
// k (fp32 [B,50,1024]) -> bf16 hi/lo padded to [B,128,1024] (rows >= 50 zero)
// ---------------------------------------------------------------------------
__global__ __launch_bounds__(256)
void ksplit(const float* __restrict__ kin, bf16* __restrict__ hi, bf16* __restrict__ lo)
{
    long long e = ((long long)blockIdx.x * 256 + threadIdx.x) * 8;   // elem index
    int b   = (int)(e >> 17);            // / (128*1024)
    int rem = (int)(e & 131071);
    int row = rem >> 10;
    int col = rem & 1023;
    float v[8] = {0,0,0,0,0,0,0,0};
    if (row < LKN) {
        const float* src = kin + ((long long)b * LKN + row) * DIN + col;
        float4 a = *(const float4*)src;
        float4 c = *(const float4*)(src + 4);
        v[0]=a.x; v[1]=a.y; v[2]=a.z; v[3]=a.w; v[4]=c.x; v[5]=c.y; v[6]=c.z; v[7]=c.w;
    }
    union { bf16 h[8]; uint4 u; } H, L;
    #pragma unroll
    for (int j = 0; j < 8; j++) split2(v[j], H.h[j], L.h[j]);
    *(uint4*)(hi + e) = H.u;
    *(uint4*)(lo + e) = L.u;
}

// ---------------------------------------------------------------------------
// scores (pre-softmax) from low-rank P:  attn[b,v,q] = (1/32) * sum_k Wo[k,v]*P[b,q,k]
// Tile 128v x 128q, K=64 (cols >= 50 of P are exact zero; Wo rows guarded).
// Skips q-tiles >= valid_len (masked by softmax anyway).
// ---------------------------------------------------------------------------
__global__ __launch_bounds__(256)
void scores_wo(const float* __restrict__ P, const float* __restrict__ Wo,
               float* __restrict__ attn, const int* __restrict__ valid)
{
    const int b  = blockIdx.z;
    const int q0 = blockIdx.x * 128;
    const int v0 = blockIdx.y * 128;
    if (q0 >= valid[b]) return;

    __shared__ float woS[64][132];
    __shared__ float pS[64][132];
    const int tid = threadIdx.x;

    // Wo tile [64k x 128v], rows >= 50 zeroed
    for (int i = tid; i < 64 * 32; i += 256) {
        int kk = i >> 5;
        int c4 = (i & 31) * 4;
        float4 w = make_float4(0.f, 0.f, 0.f, 0.f);
        if (kk < LKN) w = *(const float4*)(Wo + kk * DVN + v0 + c4);
        woS[kk][c4+0] = w.x; woS[kk][c4+1] = w.y;
        woS[kk][c4+2] = w.z; woS[kk][c4+3] = w.w;
    }
    // P tile [128q x 64k] -> transposed pS[k][q]
    for (int i = tid; i < 128 * 16; i += 256) {
        int q  = i >> 4;
        int k4 = (i & 15) * 4;
        float4 p = *(const float4*)(P + ((long long)b * LQN + q0 + q) * 128 + k4);
        pS[k4+0][q] = p.x; pS[k4+1][q] = p.y;
        pS[k4+2][q] = p.z; pS[k4+3][q] = p.w;
    }
    __syncthreads();

    const int txq = (tid & 15) * 8;
    const int tyv = (tid >> 4) * 8;
    float acc[8][8];
    #pragma unroll
    for (int i = 0; i < 8; i++)
        #pragma unroll
        for (int j = 0; j < 8; j++) acc[i][j] = 0.0f;

    #pragma unroll 8
    for (int kk = 0; kk < 64; kk++) {
        float wv[8], pq[8];
        float4 w0 = *(const float4*)&woS[kk][tyv];
        float4 w1 = *(const float4*)&woS[kk][tyv + 4];
        wv[0]=w0.x; wv[1]=w0.y; wv[2]=w0.z; wv[3]=w0.w; wv[4]=w1.x; wv[5]=w1.y; wv[6]=w1.z; wv[7]=w1.w;
        float4 p0 = *(const float4*)&pS[kk][txq];
        float4 p1 = *(const float4*)&pS[kk][txq + 4];
        pq[0]=p0.x; pq[1]=p0.y; pq[2]=p0.z; pq[3]=p0.w; pq[4]=p1.x; pq[5]=p1.y; pq[6]=p1.z; pq[7]=p1.w;
        #pragma unroll
        for (int i = 0; i < 8; i++)
            #pragma unroll
            for (int j = 0; j < 8; j++) acc[i][j] = fmaf(wv[i], pq[j], acc[i][j]);
    }

    const float s = 0.03125f;      // 1/sqrt(1024)
    #pragma unroll
    for (int i = 0; i < 8; i++) {
        int v = v0 + tyv + i;
        float* dst = attn + ((long long)b * DVN + v) * LQN + q0 + txq;
        *(float4*)dst       = make_float4(acc[i][0]*s, acc[i][1]*s, acc[i][2]*s, acc[i][3]*s);
        *(float4*)(dst + 4) = make_float4(acc[i][4]*s, acc[i][5]*s, acc[i][6]*s, acc[i][7]*s);
    }
}

// ---------------------------------------------------------------------------
// Elementwise fp32 -> bf16 hi/lo (n multiple of 2048); uint4 stores
// ---------------------------------------------------------------------------
__global__ __launch_bounds__(256)
void split_plain(const float* __restrict__ in, bf16* __restrict__ hi, bf16* __restrict__ lo)
{
    long long i = ((long long)blockIdx.x * 256 + threadIdx.x) * 8;
    float4 a = *(const float4*)(in + i);
    float4 b = *(const float4*)(in + i + 4);
    float v[8] = {a.x, a.y, a.z, a.w, b.x, b.y, b.z, b.w};
    union { bf16 h[8]; uint4 u; } H, L;
    #pragma unroll
    for (int j = 0; j < 8; j++) split2(v[j], H.h[j], L.h[j]);
    *(uint4*)(hi + i) = H.u;
    *(uint4*)(lo + i) = L.u;
}

// ---------------------------------------------------------------------------
// queries split with valid_len skip
// ---------------------------------------------------------------------------
__global__ __launch_bounds__(256)
void split_q(const float* __restrict__ in, bf16* __restrict__ hi, bf16* __restrict__ lo,
             const int* __restrict__ valid)
{
    const int b = blockIdx.x >> 10;
    const int q0 = (blockIdx.x & 1023) * 2;
    if (q0 >= valid[b]) return;
    long long base = ((long long)b * LQN + q0) * DIN;
    long long i = base + (long long)threadIdx.x * 8;
    float4 a = *(const float4*)(in + i);
    float4 c = *(const float4*)(in + i + 4);
    float v[8] = {a.x, a.y, a.z, a.w, c.x, c.y, c.z, c.w};
    union { bf16 h[8]; uint4 u; } H, L;
    #pragma unroll
    for (int j = 0; j < 8; j++) split2(v[j], H.h[j], L.h[j]);
    *(uint4*)(hi + i) = H.u;
    *(uint4*)(lo + i) = L.u;
}

// ---------------------------------------------------------------------------
// Tiled transpose + split: in [R,C] fp32 -> out [C,R] bf16 hi/lo (per batch)
// ---------------------------------------------------------------------------
__global__ __launch_bounds__(256)
void split_trans(const float* __restrict__ in, bf16* __restrict__ hi, bf16* __restrict__ lo,
                 int R, int C, const int* __restrict__ valid)
{
    const int b = blockIdx.z;
    const int r0 = blockIdx.y * 64, c0 = blockIdx.x * 32;
    if (valid) {
        int vl = valid[b];
        if (vl > 0 && r0 >= vl) return;
    }
    const long long n = (long long)R * C;
    in += b * n; hi += b * n; lo += b * n;
    __shared__ float t[32][65];
    const int lane = threadIdx.x & 31, w = threadIdx.x >> 5;
    #pragma unroll
    for (int i = 0; i < 8; i++) {
        int row = w * 8 + i;
        t[lane][row] = in[(long long)(r0 + row) * C + c0 + lane];
    }
    __syncthreads();
    #pragma unroll
    for (int p = 0; p < 4; p++) {
        int idx = threadIdx.x + p * 256;
        int c = idx >> 5;
        int rp = (idx & 31) * 2;
        bf16 h0, l0, h1, l1;
        split2(t[c][rp],     h0, l0);
        split2(t[c][rp + 1], h1, l1);
        long long off = (long long)(c0 + c) * R + r0 + rp;
        *(uint32_t*)(hi + off) = pack2b(h0, h1);
        *(uint32_t*)(lo + off) = pack2b(l0, l1);
    }
}

// ---------------------------------------------------------------------------
// Masked softmax over q (2048) per (b,v) row; emits bf16 hi/lo of attn too.
// ---------------------------------------------------------------------------
__global__ __launch_bounds__(256)
void softmax_mask(float* __restrict__ attn, const int* __restrict__ valid,
                  bf16* __restrict__ ahi, bf16* __restrict__ alo)
{
    const long long row = blockIdx.x;
    const int b = (int)(row / DVN);
    const int vl = valid[b];
    float* p = attn + row * (long long)LQN;
    const int tid = threadIdx.x;
    const int q0 = tid * 8;

    float v[8];
    {
        float4 a = *(const float4*)(p + q0);
        float4 c = *(const float4*)(p + q0 + 4);
        v[0]=a.x; v[1]=a.y; v[2]=a.z; v[3]=a.w;
        v[4]=c.x; v[5]=c.y; v[6]=c.z; v[7]=c.w;
    }
    float mx = -3.4e38f;
    #pragma unroll
    for (int i = 0; i < 8; i++) {
        v[i] = (q0 + i < vl) ? v[i] : -1000000.0f;
        mx = fmaxf(mx, v[i]);
    }
    __shared__ float red[256];
    red[tid] = mx; __syncthreads();
    for (int s = 128; s > 0; s >>= 1) { if (tid < s) red[tid] = fmaxf(red[tid], red[tid + s]); __syncthreads(); }
    mx = red[0]; __syncthreads();
    float sum = 0.0f;
    #pragma unroll
    for (int i = 0; i < 8; i++) { v[i] = expf(v[i] - mx); sum += v[i]; }
    red[tid] = sum; __syncthreads();
    for (int s = 128; s > 0; s >>= 1) { if (tid < s) red[tid] += red[tid + s]; __syncthreads(); }
    const float inv = 1.0f / red[0];

    union { bf16 h[8]; uint4 u; } H, L;
    #pragma unroll
    for (int i = 0; i < 8; i++) {
        v[i] *= inv;
        split2(v[i], H.h[i], L.h[i]);
    }
    *(float4*)(p + q0)     = make_float4(v[0], v[1], v[2], v[3]);
    *(float4*)(p + q0 + 4) = make_float4(v[4], v[5], v[6], v[7]);
    *(uint4*)(ahi + row * LQN + q0) = H.u;
    *(uint4*)(alo + row * LQN + q0) = L.u;
}

// ---------------------------------------------------------------------------
extern "C" void kernel_launch(void* const* d_in, const int* in_sizes, int n_in,
                              void* d_out, int out_size)
{
    const float* queries = (const float*)d_in[0];
    const float* keys    = (const float*)d_in[1];
    const float* values  = (const float*)d_in[2];
    const int*   valid   = (const int*)  d_in[3];
    const float* Wq      = (const float*)d_in[4];
    const float* Wk      = (const float*)d_in[5];
    const float* Wv      = (const float*)d_in[6];
    const float* Wo      = (const float*)d_in[7];

    float* out  = (float*)d_out;                         // [32,512,1024]
    float* attn = out + (size_t)BATCH * DVN * DIN;       // [32,512,2048]

    float *pk, *pP;
    bf16 *pkH, *pkL, *pWqH, *pWqL, *pZH, *pZL, *pqH, *pqL;
    bf16 *pvTH, *pvTL, *paH, *paL, *pTH, *pTL, *pWvTH, *pWvTL;
    cudaGetSymbolAddress((void**)&pk,   g_k);
    cudaGetSymbolAddress((void**)&pP,   g_P);
    cudaGetSymbolAddress((void**)&pkH,  g_kHi);  cudaGetSymbolAddress((void**)&pkL,  g_kLo);
    cudaGetSymbolAddress((void**)&pWqH, g_WqHi); cudaGetSymbolAddress((void**)&pWqL, g_WqLo);
    cudaGetSymbolAddress((void**)&pZH,  g_ZHi);  cudaGetSymbolAddress((void**)&pZL,  g_ZLo);
    cudaGetSymbolAddress((void**)&pqH,  g_qHi);  cudaGetSymbolAddress((void**)&pqL,  g_qLo);
    cudaGetSymbolAddress((void**)&pvTH, g_vTHi); cudaGetSymbolAddress((void**)&pvTL, g_vTLo);
    cudaGetSymbolAddress((void**)&paH,  g_aHi);  cudaGetSymbolAddress((void**)&paL,  g_aLo);
    cudaGetSymbolAddress((void**)&pTH,  g_THi);  cudaGetSymbolAddress((void**)&pTL,  g_TLo);
    cudaGetSymbolAddress((void**)&pWvTH, g_WvTHi); cudaGetSymbolAddress((void**)&pWvTL, g_WvTLo);

    cudaFuncSetAttribute(mma_gemm<0,0>, cudaFuncAttributeMaxDynamicSharedMemorySize, MM_SMEM_TOTAL);
    cudaFuncSetAttribute(mma_gemm<1,0>, cudaFuncAttributeMaxDynamicSharedMemorySize, MM_SMEM_TOTAL);
    cudaFuncSetAttribute(mma_gemm<0,3>, cudaFuncAttributeMaxDynamicSharedMemorySize, MM_SMEM_TOTAL);
    cudaFuncSetAttribute(mma_gemm<1,2>, cudaFuncAttributeMaxDynamicSharedMemorySize, MM_SMEM_TOTAL);

    // K1: k = keys @ W_k (fp32 SIMT, small M=50)
    gemm128<<<dim3(DIN / 128, 1, BATCH), 256>>>(
        keys, Wk, pk, LKN, DIN, DIN,
        (long long)LKN * DIN, 0, (long long)LKN * DIN, DIN, DIN, DIN);

    // k -> bf16 split, padded to 128 rows
    ksplit<<<(BATCH * 128 * DIN) / 2048, 256>>>(pk, pkH, pkL);

    // Wq -> bf16 split
    split_plain<<<(DIN * DIN) / 2048, 256>>>(Wq, pWqH, pWqL);

    // Z[b] = k_pad @ Wq^T   (M=128, N=1024, K=1024) -> bf16 split [B,128,1024]
    mma_gemm<1,0><<<dim3(DIN / 128, 1, BATCH), 256, MM_SMEM_TOTAL>>>(
        pkH, pkL, pWqH, pWqL, nullptr, pZH, pZL,
        128, DIN, DIN, (long long)128 * DIN, 0, (long long)128 * DIN, DIN, nullptr);

    // queries -> bf16 split (skip rows beyond valid_len)
    split_q<<<BATCH * (LQN / 2), 256>>>(queries, pqH, pqL, valid);

    // P[b] = queries @ Z^T   (M=2048 mask-skip, N=128, K=1024) -> fp32 [B,2048,128]
    mma_gemm<0,3><<<dim3(1, LQN / 128, BATCH), 256, MM_SMEM_TOTAL>>>(
        pqH, pqL, pZH, pZL, pP, nullptr, nullptr,
        LQN, 128, DIN, (long long)LQN * DIN, (long long)128 * DIN, (long long)LQN * 128, 128, valid);

    // scores: attn[b,v,q] = P @ Wo / 32 (fp32, q-tiles mask-skipped)
    scores_wo<<<dim3(LQN / 128, DVN / 128, BATCH), 256>>>(pP, Wo, attn, valid);

    // K5: masked softmax over q (emits bf16 split of attn)
    softmax_mask<<<BATCH * DVN, 256>>>(attn, valid, paH, paL);

    // values -> transpose+split (skip q-tiles beyond valid_len when vl>0)
    split_trans<<<dim3(DIN / 32, LQN / 64, BATCH), 256>>>(values, pvTH, pvTL, LQN, DIN, valid);

    // K6: T[v,d] = attn[v,:] . vT[d,:]  (K limited to ceil(vl/64) chunks)
    mma_gemm<1,2><<<dim3(DIN / 128, DVN / 128, BATCH), 256, MM_SMEM_TOTAL>>>(
        paH, paL, pvTH, pvTL, nullptr, pTH, pTL,
        DVN, DIN, LQN, (long long)DVN * LQN, (long long)DIN * LQN, (long long)DVN * DIN, DIN, valid);

    // Wv -> transpose+split: WvT [1024,1024]
    split_trans<<<dim3(DIN / 32, DIN / 64, 1), 256>>>(Wv, pWvTH, pWvTL, DIN, DIN, nullptr);

    // K7: out[v,h] = T[v,:] . WvT[h,:]  (M=512, N=1024, K=1024) -> fp32 out
    mma_gemm<0,0><<<dim3(DIN / 128, DVN / 128, BATCH), 256, MM_SMEM_TOTAL>>>(
        pTH, pTL, pWvTH, pWvTL, out, nullptr, nullptr,
        DVN, DIN, DIN, (long long)DVN * DIN, 0, (long long)DVN * DIN, DIN, nullptr);
}